// round 1
// baseline (speedup 1.0000x reference)
#include <cuda_runtime.h>
#include <math.h>

#define NB 2
#define NT 2048
#define NC 1024
#define NH 16
#define ND 64
#define NBH (NB*NH)
#define NM (NB*NT)   // 4096 rows

// Scratch (static device allocations — allowed; runtime allocs are not)
__device__ float g_qkv[(size_t)NM * 3 * NC];   // [4096, 3072]
__device__ float g_q[(size_t)NBH * NT * ND];   // [32, 2048, 64]
__device__ float g_k[(size_t)NBH * NT * ND];
__device__ float g_v[(size_t)NBH * NT * ND];
__device__ float g_y[(size_t)NM * NC];         // [4096, 1024] attention out (b,t,h,hd)

// ---------------------------------------------------------------------------
// SGEMM: C[M,N] = A[M,K] @ B[K,N], row-major, 128x128 block, 8x8 per thread
// ---------------------------------------------------------------------------
__global__ __launch_bounds__(256) void sgemm128(
    const float* __restrict__ A, const float* __restrict__ Bm,
    float* __restrict__ Cm, int M, int N, int K)
{
    __shared__ float As[8][128];
    __shared__ float Bs[8][128];
    const int tid = threadIdx.x;
    const int row0 = blockIdx.y * 128, col0 = blockIdx.x * 128;
    const int arow = tid >> 1, acol = (tid & 1) << 2;
    const int brow = tid >> 5, bcol = (tid & 31) << 2;
    const int tx = tid & 15, ty = tid >> 4;

    float acc[8][8];
#pragma unroll
    for (int i = 0; i < 8; i++)
#pragma unroll
        for (int j = 0; j < 8; j++) acc[i][j] = 0.f;

    const float* Aptr = A + (size_t)(row0 + arow) * K + acol;
    const float* Bptr = Bm + (size_t)brow * N + col0 + bcol;

    for (int k0 = 0; k0 < K; k0 += 8) {
        float4 a4 = *(const float4*)(Aptr + k0);
        As[acol + 0][arow] = a4.x;
        As[acol + 1][arow] = a4.y;
        As[acol + 2][arow] = a4.z;
        As[acol + 3][arow] = a4.w;
        float4 b4 = *(const float4*)(Bptr + (size_t)k0 * N);
        *(float4*)(&Bs[brow][bcol]) = b4;
        __syncthreads();
#pragma unroll
        for (int kk = 0; kk < 8; kk++) {
            float ar[8], br[8];
#pragma unroll
            for (int i = 0; i < 4; i++) {
                ar[i]     = As[kk][ty * 4 + i];
                ar[4 + i] = As[kk][64 + ty * 4 + i];
                br[i]     = Bs[kk][tx * 4 + i];
                br[4 + i] = Bs[kk][64 + tx * 4 + i];
            }
#pragma unroll
            for (int i = 0; i < 8; i++)
#pragma unroll
                for (int j = 0; j < 8; j++)
                    acc[i][j] = fmaf(ar[i], br[j], acc[i][j]);
        }
        __syncthreads();
    }
#pragma unroll
    for (int ih = 0; ih < 2; ih++)
#pragma unroll
        for (int i = 0; i < 4; i++) {
            int r = row0 + ih * 64 + ty * 4 + i;
#pragma unroll
            for (int jh = 0; jh < 2; jh++) {
                float4 v4 = make_float4(acc[ih*4+i][jh*4+0], acc[ih*4+i][jh*4+1],
                                        acc[ih*4+i][jh*4+2], acc[ih*4+i][jh*4+3]);
                *(float4*)(Cm + (size_t)r * N + col0 + jh * 64 + tx * 4) = v4;
            }
        }
}

// ---------------------------------------------------------------------------
// RoPE (roll-based) + split/transpose qkv[4096,3072] -> q/k/v [BH, T, HD]
// q_out[d] = q[d]*cos(t*f(d)) + q[(d-1)%64]*sin(t*f(d))
// ---------------------------------------------------------------------------
__global__ void rope_split(const float* __restrict__ qkv)
{
    int idx = blockIdx.x * blockDim.x + threadIdx.x;  // over BH*T*HD = 4194304
    int d  = idx & (ND - 1);
    int t  = (idx >> 6) & (NT - 1);
    int bh = idx >> 17;
    int b = bh >> 4, h = bh & (NH - 1);
    const float* base = qkv + (size_t)(b * NT + t) * (3 * NC);
    int col  = h * ND + d;
    int colm = h * ND + ((d + ND - 1) & (ND - 1));
    float qd = base[col],      qm = base[colm];
    float kd = base[NC + col], km = base[NC + colm];
    float vd = base[2 * NC + col];

    int fi = d & 31;  // concat(freqs, freqs): index mod 32
    float inv = expf(-(float)fi * (9.210340371976184f / 32.0f)); // 10000^(-fi/32)
    float ang = (float)t * inv;
    float sn, cs;
    sincosf(ang, &sn, &cs);

    g_q[idx] = qd * cs + qm * sn;
    g_k[idx] = kd * cs + km * sn;
    g_v[idx] = vd;
}

// ---------------------------------------------------------------------------
// Flash attention: 64 q-rows per block, 64-key tiles, online softmax, causal.
// smem: Qt [d][r] 64x65, KPt 64x65 (K^T then reused for P^T), Vs [c][d] 64x65
// Thread (ty,tx) owns rows 4ty..4ty+3, cols 4tx..4tx+3 of each 64x64 tile.
// ---------------------------------------------------------------------------
__global__ __launch_bounds__(256) void flash64(
    const float* __restrict__ Q, const float* __restrict__ K,
    const float* __restrict__ V, float* __restrict__ Y)
{
    extern __shared__ float sm[];
    float* Qt  = sm;               // [64][65], d-major
    float* KPt = sm + 64 * 65;     // [64][65]
    float* Vs  = sm + 2 * 64 * 65; // [64][65], c-major

    const int bh = blockIdx.y;
    const int qi = blockIdx.x;
    const int q0 = qi * 64;
    const int tid = threadIdx.x;
    const int tx = tid & 15, ty = tid >> 4;

    const float* Qb = Q + ((size_t)bh * NT + q0) * ND;
    for (int idx = tid; idx < 64 * 64; idx += 256) {
        int r = idx >> 6, d = idx & 63;
        Qt[d * 65 + r] = Qb[idx];
    }

    float m[4], l[4], o[4][4];
#pragma unroll
    for (int i = 0; i < 4; i++) {
        m[i] = -1e30f; l[i] = 0.f;
#pragma unroll
        for (int j = 0; j < 4; j++) o[i][j] = 0.f;
    }

    for (int kt = 0; kt <= qi; kt++) {
        __syncthreads();  // protect KPt/Vs readers from previous iteration
        const float* Kb = K + ((size_t)bh * NT + kt * 64) * ND;
        const float* Vb = V + ((size_t)bh * NT + kt * 64) * ND;
        for (int idx = tid; idx < 64 * 64; idx += 256) {
            int c = idx >> 6, d = idx & 63;
            KPt[d * 65 + c] = Kb[idx];
            Vs[c * 65 + d]  = Vb[idx];
        }
        __syncthreads();

        float s[4][4];
#pragma unroll
        for (int i = 0; i < 4; i++)
#pragma unroll
            for (int j = 0; j < 4; j++) s[i][j] = 0.f;

#pragma unroll 4
        for (int d = 0; d < 64; d++) {
            float a[4], bb[4];
#pragma unroll
            for (int i = 0; i < 4; i++) a[i]  = Qt[d * 65 + ty * 4 + i];
#pragma unroll
            for (int j = 0; j < 4; j++) bb[j] = KPt[d * 65 + tx * 4 + j];
#pragma unroll
            for (int i = 0; i < 4; i++)
#pragma unroll
                for (int j = 0; j < 4; j++)
                    s[i][j] = fmaf(a[i], bb[j], s[i][j]);
        }

        const bool diag = (kt == qi);
#pragma unroll
        for (int i = 0; i < 4; i++)
#pragma unroll
            for (int j = 0; j < 4; j++) {
                float vv = s[i][j] * 0.125f;  // 1/sqrt(64)
                if (diag && (tx * 4 + j) > (ty * 4 + i)) vv = -1e30f;
                s[i][j] = vv;
            }

#pragma unroll
        for (int i = 0; i < 4; i++) {
            float mt = fmaxf(fmaxf(s[i][0], s[i][1]), fmaxf(s[i][2], s[i][3]));
#pragma unroll
            for (int w = 1; w < 16; w <<= 1)
                mt = fmaxf(mt, __shfl_xor_sync(0xffffffffu, mt, w));
            float mn = fmaxf(m[i], mt);
            float alpha = __expf(m[i] - mn);
            float ls = 0.f;
#pragma unroll
            for (int j = 0; j < 4; j++) {
                float p = __expf(s[i][j] - mn);
                s[i][j] = p; ls += p;
            }
#pragma unroll
            for (int w = 1; w < 16; w <<= 1)
                ls += __shfl_xor_sync(0xffffffffu, ls, w);
            m[i] = mn;
            l[i] = l[i] * alpha + ls;
#pragma unroll
            for (int j = 0; j < 4; j++) o[i][j] *= alpha;
        }

        __syncthreads();  // done reading K^T; reuse buffer for P^T
#pragma unroll
        for (int i = 0; i < 4; i++)
#pragma unroll
            for (int j = 0; j < 4; j++)
                KPt[(tx * 4 + j) * 65 + ty * 4 + i] = s[i][j];
        __syncthreads();

#pragma unroll 4
        for (int c2 = 0; c2 < 64; c2++) {
            float p[4], vv[4];
#pragma unroll
            for (int i = 0; i < 4; i++) p[i]  = KPt[c2 * 65 + ty * 4 + i];
#pragma unroll
            for (int j = 0; j < 4; j++) vv[j] = Vs[c2 * 65 + tx * 4 + j];
#pragma unroll
            for (int i = 0; i < 4; i++)
#pragma unroll
                for (int j = 0; j < 4; j++)
                    o[i][j] = fmaf(p[i], vv[j], o[i][j]);
        }
    }

    // epilogue: normalize, write into [b, t, h, hd] = [4096, 1024]
    const int b = bh >> 4, h = bh & (NH - 1);
#pragma unroll
    for (int i = 0; i < 4; i++) {
        float inv = 1.f / l[i];
        int t = q0 + ty * 4 + i;
        float4 v4 = make_float4(o[i][0] * inv, o[i][1] * inv,
                                o[i][2] * inv, o[i][3] * inv);
        *(float4*)(Y + (size_t)(b * NT + t) * NC + h * ND + tx * 4) = v4;
    }
}

// ---------------------------------------------------------------------------
extern "C" void kernel_launch(void* const* d_in, const int* in_sizes, int n_in,
                              void* d_out, int out_size)
{
    const float* x  = (const float*)d_in[0];  // [2,2048,1024]
    const float* Wa = (const float*)d_in[1];  // [1024,3072]
    const float* Wp = (const float*)d_in[2];  // [1024,1024]
    float* out = (float*)d_out;               // [2,2048,1024]

    float *qkv, *q, *k, *v, *y;
    cudaGetSymbolAddress((void**)&qkv, g_qkv);
    cudaGetSymbolAddress((void**)&q,   g_q);
    cudaGetSymbolAddress((void**)&k,   g_k);
    cudaGetSymbolAddress((void**)&v,   g_v);
    cudaGetSymbolAddress((void**)&y,   g_y);

    // 1) QKV = x @ W_attn   [4096,1024]x[1024,3072]
    sgemm128<<<dim3(3 * NC / 128, NM / 128), 256>>>(x, Wa, qkv, NM, 3 * NC, NC);

    // 2) RoPE + head split/transpose
    rope_split<<<(NBH * NT * ND) / 256, 256>>>(qkv);

    // 3) Flash attention (causal)
    const int smem = 3 * 64 * 65 * 4;  // 49920 B
    cudaFuncSetAttribute(flash64, cudaFuncAttributeMaxDynamicSharedMemorySize, smem);
    flash64<<<dim3(NT / 64, NBH), 256, smem>>>(q, k, v, y);

    // 4) out = y @ W_proj   [4096,1024]x[1024,1024]
    sgemm128<<<dim3(NC / 128, NM / 128), 256>>>(y, Wp, out, NM, NC, NC);
}

// round 5
// speedup vs baseline: 2.0318x; 2.0318x over previous
#include <cuda_runtime.h>
#include <math.h>

#define NB 2
#define NT 2048
#define NC 1024
#define NH 16
#define ND 64
#define NBH (NB*NH)
#define NM (NB*NT)   // 4096 rows

// Scratch (static device allocations — allowed; runtime allocs are not)
__device__ float g_qkv[(size_t)NM * 3 * NC];   // [4096, 3072]
__device__ float g_q[(size_t)NBH * NT * ND];   // [32, 2048, 64]
__device__ float g_k[(size_t)NBH * NT * ND];
__device__ float g_v[(size_t)NBH * NT * ND];
__device__ float g_y[(size_t)NM * NC];         // [4096, 1024] attention out (b,t,h,hd)

// ---------------------------------------------------------------------------
// SGEMM: C[M,N] = A[M,K] @ B[K,N], row-major, 128x128 block, 8x8 per thread
// ---------------------------------------------------------------------------
__global__ __launch_bounds__(256) void sgemm128(
    const float* __restrict__ A, const float* __restrict__ Bm,
    float* __restrict__ Cm, int M, int N, int K)
{
    __shared__ float As[8][128];
    __shared__ float Bs[8][128];
    const int tid = threadIdx.x;
    const int row0 = blockIdx.y * 128, col0 = blockIdx.x * 128;
    const int arow = tid >> 1, acol = (tid & 1) << 2;
    const int brow = tid >> 5, bcol = (tid & 31) << 2;
    const int tx = tid & 15, ty = tid >> 4;

    float acc[8][8];
#pragma unroll
    for (int i = 0; i < 8; i++)
#pragma unroll
        for (int j = 0; j < 8; j++) acc[i][j] = 0.f;

    const float* Aptr = A + (size_t)(row0 + arow) * K + acol;
    const float* Bptr = Bm + (size_t)brow * N + col0 + bcol;

    for (int k0 = 0; k0 < K; k0 += 8) {
        float4 a4 = *(const float4*)(Aptr + k0);
        As[acol + 0][arow] = a4.x;
        As[acol + 1][arow] = a4.y;
        As[acol + 2][arow] = a4.z;
        As[acol + 3][arow] = a4.w;
        float4 b4 = *(const float4*)(Bptr + (size_t)k0 * N);
        *(float4*)(&Bs[brow][bcol]) = b4;
        __syncthreads();
#pragma unroll
        for (int kk = 0; kk < 8; kk++) {
            float ar[8], br[8];
#pragma unroll
            for (int i = 0; i < 4; i++) {
                ar[i]     = As[kk][ty * 4 + i];
                ar[4 + i] = As[kk][64 + ty * 4 + i];
                br[i]     = Bs[kk][tx * 4 + i];
                br[4 + i] = Bs[kk][64 + tx * 4 + i];
            }
#pragma unroll
            for (int i = 0; i < 8; i++)
#pragma unroll
                for (int j = 0; j < 8; j++)
                    acc[i][j] = fmaf(ar[i], br[j], acc[i][j]);
        }
        __syncthreads();
    }
#pragma unroll
    for (int ih = 0; ih < 2; ih++)
#pragma unroll
        for (int i = 0; i < 4; i++) {
            int r = row0 + ih * 64 + ty * 4 + i;
#pragma unroll
            for (int jh = 0; jh < 2; jh++) {
                float4 v4 = make_float4(acc[ih*4+i][jh*4+0], acc[ih*4+i][jh*4+1],
                                        acc[ih*4+i][jh*4+2], acc[ih*4+i][jh*4+3]);
                *(float4*)(Cm + (size_t)r * N + col0 + jh * 64 + tx * 4) = v4;
            }
        }
}

// ---------------------------------------------------------------------------
// RoPE (roll-based) + split/transpose qkv[4096,3072] -> q/k/v [BH, T, HD]
// ---------------------------------------------------------------------------
__global__ void rope_split(const float* __restrict__ qkv)
{
    int idx = blockIdx.x * blockDim.x + threadIdx.x;  // over BH*T*HD = 4194304
    int d  = idx & (ND - 1);
    int t  = (idx >> 6) & (NT - 1);
    int bh = idx >> 17;
    int b = bh >> 4, h = bh & (NH - 1);
    const float* base = qkv + (size_t)(b * NT + t) * (3 * NC);
    int col  = h * ND + d;
    int colm = h * ND + ((d + ND - 1) & (ND - 1));
    float qd = base[col],      qm = base[colm];
    float kd = base[NC + col], km = base[NC + colm];
    float vd = base[2 * NC + col];

    int fi = d & 31;  // concat(freqs, freqs): index mod 32
    float inv = expf(-(float)fi * (9.210340371976184f / 32.0f)); // 10000^(-fi/32)
    float ang = (float)t * inv;
    float sn, cs;
    sincosf(ang, &sn, &cs);

    g_q[idx] = qd * cs + qm * sn;
    g_k[idx] = kd * cs + km * sn;
    g_v[idx] = vd;
}

// ---------------------------------------------------------------------------
// Flash attention v2: 64 q-rows/block, 64-key tiles, online softmax, causal.
// smem (stride 68 floats = 16B-aligned rows, conflict-free LDS.128):
//   Qt  [d][r]  64x68  (Q^T)
//   KPt [d][c]  64x68  (K^T, reused as P^T [c][r])
//   Vs  [c][d]  64x68  (V natural row-major)
// Thread (ty,tx): rows 4ty..4ty+3, cols 4tx..4tx+3. All inner-loop operand
// fetches are LDS.128 (2 per d-step vs 8 scalar LDS before).
// ---------------------------------------------------------------------------
__global__ __launch_bounds__(256) void flash64(
    const float* __restrict__ Q, const float* __restrict__ K,
    const float* __restrict__ V, float* __restrict__ Y)
{
    extern __shared__ float sm[];
    float* Qt  = sm;               // [64][68]
    float* KPt = sm + 64 * 68;     // [64][68]
    float* Vs  = sm + 2 * 64 * 68; // [64][68]

    const int bh = blockIdx.y;
    const int qi = blockIdx.x;
    const int q0 = qi * 64;
    const int tid = threadIdx.x;
    const int tx = tid & 15, ty = tid >> 4;

    // Load Q tile, transpose into Qt[d][r] (float4 gmem reads, scalar STS)
    const float* Qb = Q + ((size_t)bh * NT + q0) * ND;
    for (int idx = tid; idx < 64 * 16; idx += 256) {
        int r = idx >> 4, d4 = (idx & 15) << 2;
        float4 q4 = *(const float4*)(Qb + r * ND + d4);
        Qt[(d4 + 0) * 68 + r] = q4.x;
        Qt[(d4 + 1) * 68 + r] = q4.y;
        Qt[(d4 + 2) * 68 + r] = q4.z;
        Qt[(d4 + 3) * 68 + r] = q4.w;
    }

    float m[4], l[4], o[4][4];
#pragma unroll
    for (int i = 0; i < 4; i++) {
        m[i] = -1e30f; l[i] = 0.f;
#pragma unroll
        for (int j = 0; j < 4; j++) o[i][j] = 0.f;
    }

    for (int kt = 0; kt <= qi; kt++) {
        __syncthreads();  // previous iteration's KPt/Vs readers done
        const float* Kb = K + ((size_t)bh * NT + kt * 64) * ND;
        const float* Vb = V + ((size_t)bh * NT + kt * 64) * ND;
        for (int idx = tid; idx < 64 * 16; idx += 256) {
            int r = idx >> 4, d4 = (idx & 15) << 2;
            float4 k4 = *(const float4*)(Kb + r * ND + d4);
            KPt[(d4 + 0) * 68 + r] = k4.x;
            KPt[(d4 + 1) * 68 + r] = k4.y;
            KPt[(d4 + 2) * 68 + r] = k4.z;
            KPt[(d4 + 3) * 68 + r] = k4.w;
            *(float4*)(Vs + r * 68 + d4) = *(const float4*)(Vb + r * ND + d4);
        }
        __syncthreads();

        float s[4][4];
#pragma unroll
        for (int i = 0; i < 4; i++)
#pragma unroll
            for (int j = 0; j < 4; j++) s[i][j] = 0.f;

#pragma unroll 8
        for (int d = 0; d < 64; d++) {
            float4 a4 = *(const float4*)(Qt + d * 68 + ty * 4);
            float4 b4 = *(const float4*)(KPt + d * 68 + tx * 4);
            float a[4] = {a4.x, a4.y, a4.z, a4.w};
            float bb[4] = {b4.x, b4.y, b4.z, b4.w};
#pragma unroll
            for (int i = 0; i < 4; i++)
#pragma unroll
                for (int j = 0; j < 4; j++)
                    s[i][j] = fmaf(a[i], bb[j], s[i][j]);
        }

        const bool diag = (kt == qi);
#pragma unroll
        for (int i = 0; i < 4; i++)
#pragma unroll
            for (int j = 0; j < 4; j++) {
                float vv = s[i][j] * 0.125f;  // 1/sqrt(64)
                if (diag && (tx * 4 + j) > (ty * 4 + i)) vv = -1e30f;
                s[i][j] = vv;
            }

#pragma unroll
        for (int i = 0; i < 4; i++) {
            float mt = fmaxf(fmaxf(s[i][0], s[i][1]), fmaxf(s[i][2], s[i][3]));
#pragma unroll
            for (int w = 1; w < 16; w <<= 1)
                mt = fmaxf(mt, __shfl_xor_sync(0xffffffffu, mt, w));
            float mn = fmaxf(m[i], mt);
            float alpha = __expf(m[i] - mn);
            float ls = 0.f;
#pragma unroll
            for (int j = 0; j < 4; j++) {
                float p = __expf(s[i][j] - mn);
                s[i][j] = p; ls += p;
            }
#pragma unroll
            for (int w = 1; w < 16; w <<= 1)
                ls += __shfl_xor_sync(0xffffffffu, ls, w);
            m[i] = mn;
            l[i] = l[i] * alpha + ls;
#pragma unroll
            for (int j = 0; j < 4; j++) o[i][j] *= alpha;
        }

        __syncthreads();  // done reading K^T; reuse buffer for P^T [c][r]
#pragma unroll
        for (int i = 0; i < 4; i++)
#pragma unroll
            for (int j = 0; j < 4; j++)
                KPt[(tx * 4 + j) * 68 + ty * 4 + i] = s[i][j];
        __syncthreads();

#pragma unroll 8
        for (int c2 = 0; c2 < 64; c2++) {
            float4 p4 = *(const float4*)(KPt + c2 * 68 + ty * 4);
            float4 v4 = *(const float4*)(Vs + c2 * 68 + tx * 4);
            float p[4] = {p4.x, p4.y, p4.z, p4.w};
            float vv[4] = {v4.x, v4.y, v4.z, v4.w};
#pragma unroll
            for (int i = 0; i < 4; i++)
#pragma unroll
                for (int j = 0; j < 4; j++)
                    o[i][j] = fmaf(p[i], vv[j], o[i][j]);
        }
    }

    // epilogue: normalize, write into [b, t, h, hd] = [4096, 1024]
    const int b = bh >> 4, h = bh & (NH - 1);
#pragma unroll
    for (int i = 0; i < 4; i++) {
        float inv = 1.f / l[i];
        int t = q0 + ty * 4 + i;
        float4 v4 = make_float4(o[i][0] * inv, o[i][1] * inv,
                                o[i][2] * inv, o[i][3] * inv);
        *(float4*)(Y + (size_t)(b * NT + t) * NC + h * ND + tx * 4) = v4;
    }
}

// ---------------------------------------------------------------------------
extern "C" void kernel_launch(void* const* d_in, const int* in_sizes, int n_in,
                              void* d_out, int out_size)
{
    const float* x  = (const float*)d_in[0];  // [2,2048,1024]
    const float* Wa = (const float*)d_in[1];  // [1024,3072]
    const float* Wp = (const float*)d_in[2];  // [1024,1024]
    float* out = (float*)d_out;               // [2,2048,1024]

    float *qkv, *q, *k, *v, *y;
    cudaGetSymbolAddress((void**)&qkv, g_qkv);
    cudaGetSymbolAddress((void**)&q,   g_q);
    cudaGetSymbolAddress((void**)&k,   g_k);
    cudaGetSymbolAddress((void**)&v,   g_v);
    cudaGetSymbolAddress((void**)&y,   g_y);

    // 1) QKV = x @ W_attn   [4096,1024]x[1024,3072]
    sgemm128<<<dim3(3 * NC / 128, NM / 128), 256>>>(x, Wa, qkv, NM, 3 * NC, NC);

    // 2) RoPE + head split/transpose
    rope_split<<<(NBH * NT * ND) / 256, 256>>>(qkv);

    // 3) Flash attention (causal)
    const int smem = 3 * 64 * 68 * 4;  // 52224 B
    cudaFuncSetAttribute(flash64, cudaFuncAttributeMaxDynamicSharedMemorySize, smem);
    flash64<<<dim3(NT / 64, NBH), 256, smem>>>(q, k, v, y);

    // 4) out = y @ W_proj   [4096,1024]x[1024,1024]
    sgemm128<<<dim3(NC / 128, NM / 128), 256>>>(y, Wp, out, NM, NC, NC);
}

// round 7
// speedup vs baseline: 3.1859x; 1.5680x over previous
#include <cuda_runtime.h>
#include <cuda_bf16.h>
#include <math.h>
#include <stdint.h>

#define NB 2
#define NT 2048
#define NC 1024
#define NH 16
#define ND 64
#define NBH (NB*NH)
#define NM (NB*NT)   // 4096 rows

// ---------------------------------------------------------------------------
// Scratch (static device allocations)
// ---------------------------------------------------------------------------
__device__ float g_qkv[(size_t)NM * 3 * NC];           // [4096, 3072]
__device__ float g_q[(size_t)NBH * NT * ND];
__device__ float g_k[(size_t)NBH * NT * ND];
__device__ float g_v[(size_t)NBH * NT * ND];
__device__ float g_y[(size_t)NM * NC];                 // [4096, 1024]

__device__ __nv_bfloat16 g_xh[(size_t)NM * NC];        // x hi/lo  [4096][1024]
__device__ __nv_bfloat16 g_xl[(size_t)NM * NC];
__device__ __nv_bfloat16 g_yh[(size_t)NM * NC];        // y hi/lo
__device__ __nv_bfloat16 g_yl[(size_t)NM * NC];
__device__ __nv_bfloat16 g_wah[(size_t)(3*NC) * NC];   // Wa^T hi/lo [3072][1024]
__device__ __nv_bfloat16 g_wal[(size_t)(3*NC) * NC];
__device__ __nv_bfloat16 g_wph[(size_t)NC * NC];       // Wp^T hi/lo [1024][1024]
__device__ __nv_bfloat16 g_wpl[(size_t)NC * NC];

// ---------------------------------------------------------------------------
__device__ __forceinline__ uint32_t smem_u32(const void* p) {
    uint32_t a;
    asm("{ .reg .u64 t; cvta.to.shared.u64 t, %1; cvt.u32.u64 %0, t; }"
        : "=r"(a) : "l"(p));
    return a;
}
#define SWZ(o) ((o) ^ (((o) >> 3) & 0x70))

__device__ __forceinline__ void ldsm4(uint32_t* r, uint32_t addr) {
    asm volatile("ldmatrix.sync.aligned.m8n8.x4.shared.b16 {%0,%1,%2,%3}, [%4];"
                 : "=r"(r[0]), "=r"(r[1]), "=r"(r[2]), "=r"(r[3]) : "r"(addr));
}
__device__ __forceinline__ void mma16816(float* d, const uint32_t* a, const uint32_t* b) {
    asm volatile(
        "mma.sync.aligned.m16n8k16.row.col.f32.bf16.bf16.f32 "
        "{%0,%1,%2,%3}, {%4,%5,%6,%7}, {%8,%9}, {%0,%1,%2,%3};"
        : "+f"(d[0]), "+f"(d[1]), "+f"(d[2]), "+f"(d[3])
        : "r"(a[0]), "r"(a[1]), "r"(a[2]), "r"(a[3]), "r"(b[0]), "r"(b[1]));
}

// ---------------------------------------------------------------------------
// Elementwise fp32 -> bf16 hi/lo split
// ---------------------------------------------------------------------------
__global__ void cvt_split(const float* __restrict__ in,
                          __nv_bfloat16* __restrict__ h,
                          __nv_bfloat16* __restrict__ l) {
    int i = (blockIdx.x * blockDim.x + threadIdx.x) * 4;
    float4 a = *(const float4*)(in + i);
    float v[4] = {a.x, a.y, a.z, a.w};
    __nv_bfloat16 hh[4], ll[4];
#pragma unroll
    for (int j = 0; j < 4; j++) {
        hh[j] = __float2bfloat16(v[j]);
        ll[j] = __float2bfloat16(v[j] - __bfloat162float(hh[j]));
    }
    *(__nv_bfloat162*)(h + i)     = *(__nv_bfloat162*)&hh[0];
    *(__nv_bfloat162*)(h + i + 2) = *(__nv_bfloat162*)&hh[2];
    *(__nv_bfloat162*)(l + i)     = *(__nv_bfloat162*)&ll[0];
    *(__nv_bfloat162*)(l + i + 2) = *(__nv_bfloat162*)&ll[2];
}

// ---------------------------------------------------------------------------
// W [K][N] fp32 -> W^T hi/lo [N][K] bf16 (tiled transpose + split)
// ---------------------------------------------------------------------------
__global__ void wt_split(const float* __restrict__ W,
                         __nv_bfloat16* __restrict__ Th,
                         __nv_bfloat16* __restrict__ Tl, int K, int N) {
    __shared__ float t[32][33];
    int n0 = blockIdx.x * 32, k0 = blockIdx.y * 32;
    int tx = threadIdx.x, ty0 = threadIdx.y;  // 32 x 8
#pragma unroll
    for (int i = 0; i < 4; i++) {
        int ty = ty0 + i * 8;
        t[ty][tx] = W[(size_t)(k0 + ty) * N + n0 + tx];
    }
    __syncthreads();
#pragma unroll
    for (int i = 0; i < 4; i++) {
        int ty = ty0 + i * 8;
        float a = t[tx][ty];  // = W[k0+tx][n0+ty]
        __nv_bfloat16 h = __float2bfloat16(a);
        __nv_bfloat16 l = __float2bfloat16(a - __bfloat162float(h));
        Th[(size_t)(n0 + ty) * K + k0 + tx] = h;
        Tl[(size_t)(n0 + ty) * K + k0 + tx] = l;
    }
}

// ---------------------------------------------------------------------------
// HMMA bf16x3 GEMM: C[M,N] = A @ B^T, A hi/lo [M][K], B hi/lo [N][K] (K-major).
// CTA 128x128, K-chunk 64. 8 warps in 2x4 grid: warp tile 64x32.
// mma.sync m16n8k16, fp32 accum: Ah*Bh + Ah*Bl + Al*Bh.
// smem tiles 128 rows x 64 bf16 (128B rows) SW128-swizzled; ldmatrix operands.
// ---------------------------------------------------------------------------
__global__ __launch_bounds__(256, 2) void gemm_mma(
    const __nv_bfloat16* __restrict__ Ah, const __nv_bfloat16* __restrict__ Al,
    const __nv_bfloat16* __restrict__ Bh, const __nv_bfloat16* __restrict__ Bl,
    float* __restrict__ C, int M, int N, int K) {
    extern __shared__ char smem[];
    const uint32_t sb = smem_u32(smem);
    const uint32_t sAh = sb, sAl = sb + 16384, sBh = sb + 32768, sBl = sb + 49152;

    const int tid = threadIdx.x, wid = tid >> 5, lane = tid & 31;
    const int m0 = blockIdx.y * 128, n0 = blockIdx.x * 128;
    const int wm0 = (wid >> 2) * 64, wn0 = (wid & 3) * 32;

    // ldmatrix per-lane address components (tile-relative).
    // A frag i (m16): lanes 0-15 -> rows m+0..15 k-bytes +0, lanes 16-31 -> +16
    uint32_t a_r[4], a_s[4];
#pragma unroll
    for (int i = 0; i < 4; i++) {
        int row = wm0 + 16 * i + (lane & 15);
        a_r[i] = row * 128;
        a_s[i] = (row & 7) * 16;
    }
    const uint32_t gA = (lane >> 4) * 16;
    // B frag j (n16): g0 rows n+0..7 kb0, g1 rows n+0..7 kb16, g2 n+8..15 kb0, g3 kb16
    uint32_t b_r[2], b_s[2];
#pragma unroll
    for (int j = 0; j < 2; j++) {
        int row = wn0 + 16 * j + (lane & 7) + ((lane >> 4) << 3);
        b_r[j] = row * 128;
        b_s[j] = (row & 7) * 16;
    }
    const uint32_t gB = ((lane >> 3) & 1) * 16;

    float acc[4][4][4];
#pragma unroll
    for (int i = 0; i < 4; i++)
#pragma unroll
        for (int j = 0; j < 4; j++)
#pragma unroll
            for (int q = 0; q < 4; q++) acc[i][j][q] = 0.f;

    const int nch = K / 64;
    for (int c = 0; c < nch; c++) {
        const int k0 = c * 64;
        if (c) __syncthreads();  // previous chunk's readers done
        // ---- load 4 tiles (128 rows x 64 bf16 = 16KB each) ----
#pragma unroll
        for (int t = 0; t < 4; t++) {
            const __nv_bfloat16* base =
                (t == 0) ? Ah + (size_t)m0 * K :
                (t == 1) ? Al + (size_t)m0 * K :
                (t == 2) ? Bh + (size_t)n0 * K :
                           Bl + (size_t)n0 * K;
            uint32_t dstb = sAh + t * 16384;
#pragma unroll
            for (int i = 0; i < 4; i++) {
                int idx = tid + i * 256;        // 0..1023
                int r = idx >> 3, c8 = idx & 7;
                uint4 v = *(const uint4*)(base + (size_t)r * K + k0 + c8 * 8);
                uint32_t d = dstb + SWZ(r * 128 + c8 * 16);
                asm volatile("st.shared.v4.b32 [%0], {%1,%2,%3,%4};"
                             :: "r"(d), "r"(v.x), "r"(v.y), "r"(v.z), "r"(v.w));
            }
        }
        __syncthreads();

        // ---- 4 k16 steps ----
#pragma unroll
        for (int ks = 0; ks < 4; ks++) {
            const uint32_t ks32 = ks * 32;
            uint32_t af[4][4], bh2[2][4], bl2[2][4];
#pragma unroll
            for (int i = 0; i < 4; i++)
                ldsm4(af[i], sAh + a_r[i] + ((ks32 + gA) ^ a_s[i]));
#pragma unroll
            for (int j = 0; j < 2; j++) {
                ldsm4(bh2[j], sBh + b_r[j] + ((ks32 + gB) ^ b_s[j]));
                ldsm4(bl2[j], sBl + b_r[j] + ((ks32 + gB) ^ b_s[j]));
            }
            // Ah*Bh and Ah*Bl
#pragma unroll
            for (int i = 0; i < 4; i++)
#pragma unroll
                for (int j = 0; j < 2; j++) {
                    mma16816(acc[i][j * 2 + 0], af[i], &bh2[j][0]);
                    mma16816(acc[i][j * 2 + 1], af[i], &bh2[j][2]);
                }
#pragma unroll
            for (int i = 0; i < 4; i++)
#pragma unroll
                for (int j = 0; j < 2; j++) {
                    mma16816(acc[i][j * 2 + 0], af[i], &bl2[j][0]);
                    mma16816(acc[i][j * 2 + 1], af[i], &bl2[j][2]);
                }
            // Al*Bh (reuse af regs)
#pragma unroll
            for (int i = 0; i < 4; i++)
                ldsm4(af[i], sAl + a_r[i] + ((ks32 + gA) ^ a_s[i]));
#pragma unroll
            for (int i = 0; i < 4; i++)
#pragma unroll
                for (int j = 0; j < 2; j++) {
                    mma16816(acc[i][j * 2 + 0], af[i], &bh2[j][0]);
                    mma16816(acc[i][j * 2 + 1], af[i], &bh2[j][2]);
                }
        }
    }

    // ---- epilogue: c0,c1 -> row lane/4, cols (lane%4)*2; c2,c3 -> row+8 ----
    const int er = lane >> 2, ec = (lane & 3) * 2;
#pragma unroll
    for (int i = 0; i < 4; i++) {
        int r = m0 + wm0 + 16 * i + er;
#pragma unroll
        for (int j = 0; j < 4; j++) {
            int col = n0 + wn0 + 8 * j + ec;
            *(float2*)(C + (size_t)r * N + col)       = make_float2(acc[i][j][0], acc[i][j][1]);
            *(float2*)(C + (size_t)(r + 8) * N + col) = make_float2(acc[i][j][2], acc[i][j][3]);
        }
    }
}

// ---------------------------------------------------------------------------
// RoPE (roll-based) + split/transpose qkv[4096,3072] -> q/k/v [BH, T, HD]
// ---------------------------------------------------------------------------
__global__ void rope_split(const float* __restrict__ qkv)
{
    int idx = blockIdx.x * blockDim.x + threadIdx.x;
    int d  = idx & (ND - 1);
    int t  = (idx >> 6) & (NT - 1);
    int bh = idx >> 17;
    int b = bh >> 4, h = bh & (NH - 1);
    const float* base = qkv + (size_t)(b * NT + t) * (3 * NC);
    int col  = h * ND + d;
    int colm = h * ND + ((d + ND - 1) & (ND - 1));
    float qd = base[col],      qm = base[colm];
    float kd = base[NC + col], km = base[NC + colm];
    float vd = base[2 * NC + col];

    int fi = d & 31;
    float inv = expf(-(float)fi * (9.210340371976184f / 32.0f));
    float ang = (float)t * inv;
    float sn, cs;
    sincosf(ang, &sn, &cs);

    g_q[idx] = qd * cs + qm * sn;
    g_k[idx] = kd * cs + km * sn;
    g_v[idx] = vd;
}

// ---------------------------------------------------------------------------
// Flash attention (unchanged from round 5)
// ---------------------------------------------------------------------------
__global__ __launch_bounds__(256) void flash64(
    const float* __restrict__ Q, const float* __restrict__ K,
    const float* __restrict__ V, float* __restrict__ Y)
{
    extern __shared__ float sm[];
    float* Qt  = sm;
    float* KPt = sm + 64 * 68;
    float* Vs  = sm + 2 * 64 * 68;

    const int bh = blockIdx.y;
    const int qi = blockIdx.x;
    const int q0 = qi * 64;
    const int tid = threadIdx.x;
    const int tx = tid & 15, ty = tid >> 4;

    const float* Qb = Q + ((size_t)bh * NT + q0) * ND;
    for (int idx = tid; idx < 64 * 16; idx += 256) {
        int r = idx >> 4, d4 = (idx & 15) << 2;
        float4 q4 = *(const float4*)(Qb + r * ND + d4);
        Qt[(d4 + 0) * 68 + r] = q4.x;
        Qt[(d4 + 1) * 68 + r] = q4.y;
        Qt[(d4 + 2) * 68 + r] = q4.z;
        Qt[(d4 + 3) * 68 + r] = q4.w;
    }

    float m[4], l[4], o[4][4];
#pragma unroll
    for (int i = 0; i < 4; i++) {
        m[i] = -1e30f; l[i] = 0.f;
#pragma unroll
        for (int j = 0; j < 4; j++) o[i][j] = 0.f;
    }

    for (int kt = 0; kt <= qi; kt++) {
        __syncthreads();
        const float* Kb = K + ((size_t)bh * NT + kt * 64) * ND;
        const float* Vb = V + ((size_t)bh * NT + kt * 64) * ND;
        for (int idx = tid; idx < 64 * 16; idx += 256) {
            int r = idx >> 4, d4 = (idx & 15) << 2;
            float4 k4 = *(const float4*)(Kb + r * ND + d4);
            KPt[(d4 + 0) * 68 + r] = k4.x;
            KPt[(d4 + 1) * 68 + r] = k4.y;
            KPt[(d4 + 2) * 68 + r] = k4.z;
            KPt[(d4 + 3) * 68 + r] = k4.w;
            *(float4*)(Vs + r * 68 + d4) = *(const float4*)(Vb + r * ND + d4);
        }
        __syncthreads();

        float s[4][4];
#pragma unroll
        for (int i = 0; i < 4; i++)
#pragma unroll
            for (int j = 0; j < 4; j++) s[i][j] = 0.f;

#pragma unroll 8
        for (int d = 0; d < 64; d++) {
            float4 a4 = *(const float4*)(Qt + d * 68 + ty * 4);
            float4 b4 = *(const float4*)(KPt + d * 68 + tx * 4);
            float a[4] = {a4.x, a4.y, a4.z, a4.w};
            float bb[4] = {b4.x, b4.y, b4.z, b4.w};
#pragma unroll
            for (int i = 0; i < 4; i++)
#pragma unroll
                for (int j = 0; j < 4; j++)
                    s[i][j] = fmaf(a[i], bb[j], s[i][j]);
        }

        const bool diag = (kt == qi);
#pragma unroll
        for (int i = 0; i < 4; i++)
#pragma unroll
            for (int j = 0; j < 4; j++) {
                float vv = s[i][j] * 0.125f;
                if (diag && (tx * 4 + j) > (ty * 4 + i)) vv = -1e30f;
                s[i][j] = vv;
            }

#pragma unroll
        for (int i = 0; i < 4; i++) {
            float mt = fmaxf(fmaxf(s[i][0], s[i][1]), fmaxf(s[i][2], s[i][3]));
#pragma unroll
            for (int w = 1; w < 16; w <<= 1)
                mt = fmaxf(mt, __shfl_xor_sync(0xffffffffu, mt, w));
            float mn = fmaxf(m[i], mt);
            float alpha = __expf(m[i] - mn);
            float ls = 0.f;
#pragma unroll
            for (int j = 0; j < 4; j++) {
                float p = __expf(s[i][j] - mn);
                s[i][j] = p; ls += p;
            }
#pragma unroll
            for (int w = 1; w < 16; w <<= 1)
                ls += __shfl_xor_sync(0xffffffffu, ls, w);
            m[i] = mn;
            l[i] = l[i] * alpha + ls;
#pragma unroll
            for (int j = 0; j < 4; j++) o[i][j] *= alpha;
        }

        __syncthreads();
#pragma unroll
        for (int i = 0; i < 4; i++)
#pragma unroll
            for (int j = 0; j < 4; j++)
                KPt[(tx * 4 + j) * 68 + ty * 4 + i] = s[i][j];
        __syncthreads();

#pragma unroll 8
        for (int c2 = 0; c2 < 64; c2++) {
            float4 p4 = *(const float4*)(KPt + c2 * 68 + ty * 4);
            float4 v4 = *(const float4*)(Vs + c2 * 68 + tx * 4);
            float p[4] = {p4.x, p4.y, p4.z, p4.w};
            float vv[4] = {v4.x, v4.y, v4.z, v4.w};
#pragma unroll
            for (int i = 0; i < 4; i++)
#pragma unroll
                for (int j = 0; j < 4; j++)
                    o[i][j] = fmaf(p[i], vv[j], o[i][j]);
        }
    }

    const int b = bh >> 4, h = bh & (NH - 1);
#pragma unroll
    for (int i = 0; i < 4; i++) {
        float inv = 1.f / l[i];
        int t = q0 + ty * 4 + i;
        float4 v4 = make_float4(o[i][0] * inv, o[i][1] * inv,
                                o[i][2] * inv, o[i][3] * inv);
        *(float4*)(Y + (size_t)(b * NT + t) * NC + h * ND + tx * 4) = v4;
    }
}

// ---------------------------------------------------------------------------
extern "C" void kernel_launch(void* const* d_in, const int* in_sizes, int n_in,
                              void* d_out, int out_size)
{
    const float* x  = (const float*)d_in[0];  // [2,2048,1024]
    const float* Wa = (const float*)d_in[1];  // [1024,3072]
    const float* Wp = (const float*)d_in[2];  // [1024,1024]
    float* out = (float*)d_out;               // [2,2048,1024]

    float *qkv, *q, *k, *v, *y;
    __nv_bfloat16 *xh, *xl, *yh, *yl, *wah, *wal, *wph, *wpl;
    cudaGetSymbolAddress((void**)&qkv, g_qkv);
    cudaGetSymbolAddress((void**)&q,   g_q);
    cudaGetSymbolAddress((void**)&k,   g_k);
    cudaGetSymbolAddress((void**)&v,   g_v);
    cudaGetSymbolAddress((void**)&y,   g_y);
    cudaGetSymbolAddress((void**)&xh,  g_xh);
    cudaGetSymbolAddress((void**)&xl,  g_xl);
    cudaGetSymbolAddress((void**)&yh,  g_yh);
    cudaGetSymbolAddress((void**)&yl,  g_yl);
    cudaGetSymbolAddress((void**)&wah, g_wah);
    cudaGetSymbolAddress((void**)&wal, g_wal);
    cudaGetSymbolAddress((void**)&wph, g_wph);
    cudaGetSymbolAddress((void**)&wpl, g_wpl);

    const int gemm_smem = 65536;
    cudaFuncSetAttribute(gemm_mma, cudaFuncAttributeMaxDynamicSharedMemorySize, gemm_smem);

    // 0) splits / transposes
    cvt_split<<<(NM * NC) / 1024, 256>>>(x, xh, xl);
    wt_split<<<dim3(3 * NC / 32, NC / 32), dim3(32, 8)>>>(Wa, wah, wal, NC, 3 * NC);
    wt_split<<<dim3(NC / 32, NC / 32), dim3(32, 8)>>>(Wp, wph, wpl, NC, NC);

    // 1) QKV = x @ W_attn  via HMMA bf16x3
    gemm_mma<<<dim3(3 * NC / 128, NM / 128), 256, gemm_smem>>>(
        xh, xl, wah, wal, qkv, NM, 3 * NC, NC);

    // 2) RoPE + head split/transpose
    rope_split<<<(NBH * NT * ND) / 256, 256>>>(qkv);

    // 3) Flash attention (causal)
    const int smem = 3 * 64 * 68 * 4;  // 52224 B
    cudaFuncSetAttribute(flash64, cudaFuncAttributeMaxDynamicSharedMemorySize, smem);
    flash64<<<dim3(NT / 64, NBH), 256, smem>>>(q, k, v, y);

    // 4) out = y @ W_proj  via HMMA bf16x3
    cvt_split<<<(NM * NC) / 1024, 256>>>(y, yh, yl);
    gemm_mma<<<dim3(NC / 128, NM / 128), 256, gemm_smem>>>(
        yh, yl, wph, wpl, out, NM, NC, NC);
}

// round 8
// speedup vs baseline: 5.9917x; 1.8807x over previous
#include <cuda_runtime.h>
#include <cuda_bf16.h>
#include <math.h>
#include <stdint.h>

#define NB 2
#define NT 2048
#define NC 1024
#define NH 16
#define ND 64
#define NBH (NB*NH)
#define NM (NB*NT)   // 4096 rows

// ---------------------------------------------------------------------------
// Scratch (static device allocations)
// ---------------------------------------------------------------------------
__device__ float g_qkv[(size_t)NM * 3 * NC];            // [4096, 3072]

__device__ __nv_bfloat16 g_xh[(size_t)NM * NC];         // x hi/lo
__device__ __nv_bfloat16 g_xl[(size_t)NM * NC];
__device__ __nv_bfloat16 g_yh[(size_t)NM * NC];         // attn out hi/lo
__device__ __nv_bfloat16 g_yl[(size_t)NM * NC];
__device__ __nv_bfloat16 g_wah[(size_t)(3*NC) * NC];    // Wa^T hi/lo [3072][1024]
__device__ __nv_bfloat16 g_wal[(size_t)(3*NC) * NC];
__device__ __nv_bfloat16 g_wph[(size_t)NC * NC];        // Wp^T hi/lo
__device__ __nv_bfloat16 g_wpl[(size_t)NC * NC];

__device__ __nv_bfloat16 g_qh[(size_t)NBH * NT * ND];   // RoPE'd Q*scale hi/lo
__device__ __nv_bfloat16 g_ql[(size_t)NBH * NT * ND];
__device__ __nv_bfloat16 g_kh[(size_t)NBH * NT * ND];
__device__ __nv_bfloat16 g_kl[(size_t)NBH * NT * ND];
__device__ __nv_bfloat16 g_vh[(size_t)NBH * NT * ND];
__device__ __nv_bfloat16 g_vl[(size_t)NBH * NT * ND];

// ---------------------------------------------------------------------------
__device__ __forceinline__ uint32_t smem_u32(const void* p) {
    uint32_t a;
    asm("{ .reg .u64 t; cvta.to.shared.u64 t, %1; cvt.u32.u64 %0, t; }"
        : "=r"(a) : "l"(p));
    return a;
}
#define SWZ(o) ((o) ^ (((o) >> 3) & 0x70))

__device__ __forceinline__ void ldsm4(uint32_t* r, uint32_t addr) {
    asm volatile("ldmatrix.sync.aligned.m8n8.x4.shared.b16 {%0,%1,%2,%3}, [%4];"
                 : "=r"(r[0]), "=r"(r[1]), "=r"(r[2]), "=r"(r[3]) : "r"(addr));
}
__device__ __forceinline__ void ldsm4t(uint32_t* r, uint32_t addr) {
    asm volatile("ldmatrix.sync.aligned.m8n8.x4.trans.shared.b16 {%0,%1,%2,%3}, [%4];"
                 : "=r"(r[0]), "=r"(r[1]), "=r"(r[2]), "=r"(r[3]) : "r"(addr));
}
__device__ __forceinline__ void mma16816(float* d, const uint32_t* a, const uint32_t* b) {
    asm volatile(
        "mma.sync.aligned.m16n8k16.row.col.f32.bf16.bf16.f32 "
        "{%0,%1,%2,%3}, {%4,%5,%6,%7}, {%8,%9}, {%0,%1,%2,%3};"
        : "+f"(d[0]), "+f"(d[1]), "+f"(d[2]), "+f"(d[3])
        : "r"(a[0]), "r"(a[1]), "r"(a[2]), "r"(a[3]), "r"(b[0]), "r"(b[1]));
}
// pack two fp32 -> bf16x2 (lo = first arg -> low 16 bits)
__device__ __forceinline__ uint32_t packf(float lo, float hi) {
    uint32_t d;
    asm("cvt.rn.bf16x2.f32 %0, %1, %2;" : "=r"(d) : "f"(hi), "f"(lo));
    return d;
}

// ---------------------------------------------------------------------------
// Elementwise fp32 -> bf16 hi/lo split
// ---------------------------------------------------------------------------
__global__ void cvt_split(const float* __restrict__ in,
                          __nv_bfloat16* __restrict__ h,
                          __nv_bfloat16* __restrict__ l) {
    int i = (blockIdx.x * blockDim.x + threadIdx.x) * 4;
    float4 a = *(const float4*)(in + i);
    float v[4] = {a.x, a.y, a.z, a.w};
    __nv_bfloat16 hh[4], ll[4];
#pragma unroll
    for (int j = 0; j < 4; j++) {
        hh[j] = __float2bfloat16(v[j]);
        ll[j] = __float2bfloat16(v[j] - __bfloat162float(hh[j]));
    }
    *(__nv_bfloat162*)(h + i)     = *(__nv_bfloat162*)&hh[0];
    *(__nv_bfloat162*)(h + i + 2) = *(__nv_bfloat162*)&hh[2];
    *(__nv_bfloat162*)(l + i)     = *(__nv_bfloat162*)&ll[0];
    *(__nv_bfloat162*)(l + i + 2) = *(__nv_bfloat162*)&ll[2];
}

// ---------------------------------------------------------------------------
// W [K][N] fp32 -> W^T hi/lo [N][K] bf16
// ---------------------------------------------------------------------------
__global__ void wt_split(const float* __restrict__ W,
                         __nv_bfloat16* __restrict__ Th,
                         __nv_bfloat16* __restrict__ Tl, int K, int N) {
    __shared__ float t[32][33];
    int n0 = blockIdx.x * 32, k0 = blockIdx.y * 32;
    int tx = threadIdx.x, ty0 = threadIdx.y;
#pragma unroll
    for (int i = 0; i < 4; i++) {
        int ty = ty0 + i * 8;
        t[ty][tx] = W[(size_t)(k0 + ty) * N + n0 + tx];
    }
    __syncthreads();
#pragma unroll
    for (int i = 0; i < 4; i++) {
        int ty = ty0 + i * 8;
        float a = t[tx][ty];
        __nv_bfloat16 h = __float2bfloat16(a);
        __nv_bfloat16 l = __float2bfloat16(a - __bfloat162float(h));
        Th[(size_t)(n0 + ty) * K + k0 + tx] = h;
        Tl[(size_t)(n0 + ty) * K + k0 + tx] = l;
    }
}

// ---------------------------------------------------------------------------
// HMMA bf16x3 GEMM (unchanged from round 7)
// ---------------------------------------------------------------------------
__global__ __launch_bounds__(256, 2) void gemm_mma(
    const __nv_bfloat16* __restrict__ Ah, const __nv_bfloat16* __restrict__ Al,
    const __nv_bfloat16* __restrict__ Bh, const __nv_bfloat16* __restrict__ Bl,
    float* __restrict__ C, int M, int N, int K) {
    extern __shared__ char smem[];
    const uint32_t sb = smem_u32(smem);
    const uint32_t sAh = sb, sAl = sb + 16384, sBh = sb + 32768, sBl = sb + 49152;

    const int tid = threadIdx.x, wid = tid >> 5, lane = tid & 31;
    const int m0 = blockIdx.y * 128, n0 = blockIdx.x * 128;
    const int wm0 = (wid >> 2) * 64, wn0 = (wid & 3) * 32;

    uint32_t a_r[4], a_s[4];
#pragma unroll
    for (int i = 0; i < 4; i++) {
        int row = wm0 + 16 * i + (lane & 15);
        a_r[i] = row * 128;
        a_s[i] = (row & 7) * 16;
    }
    const uint32_t gA = (lane >> 4) * 16;
    uint32_t b_r[2], b_s[2];
#pragma unroll
    for (int j = 0; j < 2; j++) {
        int row = wn0 + 16 * j + (lane & 7) + ((lane >> 4) << 3);
        b_r[j] = row * 128;
        b_s[j] = (row & 7) * 16;
    }
    const uint32_t gB = ((lane >> 3) & 1) * 16;

    float acc[4][4][4];
#pragma unroll
    for (int i = 0; i < 4; i++)
#pragma unroll
        for (int j = 0; j < 4; j++)
#pragma unroll
            for (int q = 0; q < 4; q++) acc[i][j][q] = 0.f;

    const int nch = K / 64;
    for (int c = 0; c < nch; c++) {
        const int k0 = c * 64;
        if (c) __syncthreads();
#pragma unroll
        for (int t = 0; t < 4; t++) {
            const __nv_bfloat16* base =
                (t == 0) ? Ah + (size_t)m0 * K :
                (t == 1) ? Al + (size_t)m0 * K :
                (t == 2) ? Bh + (size_t)n0 * K :
                           Bl + (size_t)n0 * K;
            uint32_t dstb = sAh + t * 16384;
#pragma unroll
            for (int i = 0; i < 4; i++) {
                int idx = tid + i * 256;
                int r = idx >> 3, c8 = idx & 7;
                uint4 v = *(const uint4*)(base + (size_t)r * K + k0 + c8 * 8);
                uint32_t d = dstb + SWZ(r * 128 + c8 * 16);
                asm volatile("st.shared.v4.b32 [%0], {%1,%2,%3,%4};"
                             :: "r"(d), "r"(v.x), "r"(v.y), "r"(v.z), "r"(v.w));
            }
        }
        __syncthreads();

#pragma unroll
        for (int ks = 0; ks < 4; ks++) {
            const uint32_t ks32 = ks * 32;
            uint32_t af[4][4], bh2[2][4], bl2[2][4];
#pragma unroll
            for (int i = 0; i < 4; i++)
                ldsm4(af[i], sAh + a_r[i] + ((ks32 + gA) ^ a_s[i]));
#pragma unroll
            for (int j = 0; j < 2; j++) {
                ldsm4(bh2[j], sBh + b_r[j] + ((ks32 + gB) ^ b_s[j]));
                ldsm4(bl2[j], sBl + b_r[j] + ((ks32 + gB) ^ b_s[j]));
            }
#pragma unroll
            for (int i = 0; i < 4; i++)
#pragma unroll
                for (int j = 0; j < 2; j++) {
                    mma16816(acc[i][j * 2 + 0], af[i], &bh2[j][0]);
                    mma16816(acc[i][j * 2 + 1], af[i], &bh2[j][2]);
                }
#pragma unroll
            for (int i = 0; i < 4; i++)
#pragma unroll
                for (int j = 0; j < 2; j++) {
                    mma16816(acc[i][j * 2 + 0], af[i], &bl2[j][0]);
                    mma16816(acc[i][j * 2 + 1], af[i], &bl2[j][2]);
                }
#pragma unroll
            for (int i = 0; i < 4; i++)
                ldsm4(af[i], sAl + a_r[i] + ((ks32 + gA) ^ a_s[i]));
#pragma unroll
            for (int i = 0; i < 4; i++)
#pragma unroll
                for (int j = 0; j < 2; j++) {
                    mma16816(acc[i][j * 2 + 0], af[i], &bh2[j][0]);
                    mma16816(acc[i][j * 2 + 1], af[i], &bh2[j][2]);
                }
        }
    }

    const int er = lane >> 2, ec = (lane & 3) * 2;
#pragma unroll
    for (int i = 0; i < 4; i++) {
        int r = m0 + wm0 + 16 * i + er;
#pragma unroll
        for (int j = 0; j < 4; j++) {
            int col = n0 + wn0 + 8 * j + ec;
            *(float2*)(C + (size_t)r * N + col)       = make_float2(acc[i][j][0], acc[i][j][1]);
            *(float2*)(C + (size_t)(r + 8) * N + col) = make_float2(acc[i][j][2], acc[i][j][3]);
        }
    }
}

// ---------------------------------------------------------------------------
// RoPE + head split; emit bf16 hi/lo Q(*0.125)/K/V in [BH][T][64]
// ---------------------------------------------------------------------------
__global__ void rope_split(const float* __restrict__ qkv)
{
    int idx = blockIdx.x * blockDim.x + threadIdx.x;
    int d  = idx & (ND - 1);
    int t  = (idx >> 6) & (NT - 1);
    int bh = idx >> 17;
    int b = bh >> 4, h = bh & (NH - 1);
    const float* base = qkv + (size_t)(b * NT + t) * (3 * NC);
    int col  = h * ND + d;
    int colm = h * ND + ((d + ND - 1) & (ND - 1));
    float qd = base[col],      qm = base[colm];
    float kd = base[NC + col], km = base[NC + colm];
    float vd = base[2 * NC + col];

    int fi = d & 31;
    float inv = expf(-(float)fi * (9.210340371976184f / 32.0f));
    float ang = (float)t * inv;
    float sn, cs;
    sincosf(ang, &sn, &cs);

    float qv = (qd * cs + qm * sn) * 0.125f;   // fold 1/sqrt(64)
    float kv = kd * cs + km * sn;

    __nv_bfloat16 hh;
    hh = __float2bfloat16(qv);
    g_qh[idx] = hh; g_ql[idx] = __float2bfloat16(qv - __bfloat162float(hh));
    hh = __float2bfloat16(kv);
    g_kh[idx] = hh; g_kl[idx] = __float2bfloat16(kv - __bfloat162float(hh));
    hh = __float2bfloat16(vd);
    g_vh[idx] = hh; g_vl[idx] = __float2bfloat16(vd - __bfloat162float(hh));
}

// ---------------------------------------------------------------------------
// Flash attention on HMMA. CTA: 128 q-rows, 64-key tiles, 8 warps x 16 rows.
// S = Qh*Kh + Qh*Kl + Ql*Kh (scale pre-folded); online softmax in registers;
// P repacked from accumulators (hi + residual lo); O += Ph*Vh + Ph*Vl + Pl*Vh
// with V fragments via ldmatrix.trans. Emits yh/yl bf16 for the proj GEMM.
// ---------------------------------------------------------------------------
__global__ __launch_bounds__(256, 2) void flash_mma(
    const __nv_bfloat16* __restrict__ Qh_, const __nv_bfloat16* __restrict__ Ql_,
    const __nv_bfloat16* __restrict__ Kh_, const __nv_bfloat16* __restrict__ Kl_,
    const __nv_bfloat16* __restrict__ Vh_, const __nv_bfloat16* __restrict__ Vl_,
    __nv_bfloat16* __restrict__ Yh_, __nv_bfloat16* __restrict__ Yl_)
{
    extern __shared__ char smem[];
    const uint32_t sb = smem_u32(smem);
    const uint32_t sQh = sb, sQl = sb + 16384;
    const uint32_t sKh = sb + 32768, sKl = sb + 40960;
    const uint32_t sVh = sb + 49152, sVl = sb + 57344;

    const int bh = blockIdx.y, qi = blockIdx.x, q0 = qi * 128;
    const int tid = threadIdx.x, wid = tid >> 5, lane = tid & 31;
    const int wm = wid * 16;
    const size_t gbase = (size_t)bh * NT * ND;

    // ---- load Q hi/lo (128x64) ----
    {
        const __nv_bfloat16* s0 = Qh_ + gbase + (size_t)q0 * ND;
        const __nv_bfloat16* s1 = Ql_ + gbase + (size_t)q0 * ND;
#pragma unroll
        for (int i = 0; i < 4; i++) {
            int idx = tid + i * 256;
            int r = idx >> 3, c8 = idx & 7;
            uint32_t off = SWZ(r * 128 + c8 * 16);
            uint4 v = *(const uint4*)(s0 + (size_t)r * ND + c8 * 8);
            asm volatile("st.shared.v4.b32 [%0], {%1,%2,%3,%4};"
                         :: "r"(sQh + off), "r"(v.x), "r"(v.y), "r"(v.z), "r"(v.w));
            uint4 w = *(const uint4*)(s1 + (size_t)r * ND + c8 * 8);
            asm volatile("st.shared.v4.b32 [%0], {%1,%2,%3,%4};"
                         :: "r"(sQl + off), "r"(w.x), "r"(w.y), "r"(w.z), "r"(w.w));
        }
    }

    // per-lane fragment address components
    const int rowA = wm + (lane & 15);
    const uint32_t aoff = rowA * 128, aswz = (rowA & 7) * 16;
    const uint32_t gA = (lane >> 4) * 16;
    const int rowB_ = (lane & 7) + ((lane >> 4) << 3);        // K (non-trans)
    const uint32_t bswz = (rowB_ & 7) * 16;
    const uint32_t gB = ((lane >> 3) & 1) * 16;
    const int rowV_ = ((lane >> 3) & 1) * 8 + (lane & 7);     // V (trans)
    const uint32_t vswz = (lane & 7) * 16;
    const uint32_t gV = (lane >> 4) * 16;

    float m0 = -1e30f, m1 = -1e30f, l0 = 0.f, l1 = 0.f;
    float oacc[8][4];
#pragma unroll
    for (int j = 0; j < 8; j++)
#pragma unroll
        for (int e = 0; e < 4; e++) oacc[j][e] = 0.f;

    const int nkt = 2 * qi + 2;
    for (int kt = 0; kt < nkt; kt++) {
        __syncthreads();   // smem safe to overwrite (also covers Q store at kt=0)
        {
            const size_t koff = gbase + (size_t)kt * 64 * ND;
            const __nv_bfloat16* srcs[4] = {Kh_ + koff, Kl_ + koff, Vh_ + koff, Vl_ + koff};
            const uint32_t dsts[4] = {sKh, sKl, sVh, sVl};
#pragma unroll
            for (int t = 0; t < 4; t++)
#pragma unroll
                for (int i = 0; i < 2; i++) {
                    int idx = tid + i * 256;
                    int r = idx >> 3, c8 = idx & 7;
                    uint4 v = *(const uint4*)(srcs[t] + (size_t)r * ND + c8 * 8);
                    uint32_t d = dsts[t] + SWZ(r * 128 + c8 * 16);
                    asm volatile("st.shared.v4.b32 [%0], {%1,%2,%3,%4};"
                                 :: "r"(d), "r"(v.x), "r"(v.y), "r"(v.z), "r"(v.w));
                }
        }
        __syncthreads();

        if (kt * 64 > q0 + wm + 15) continue;   // fully-masked for this warp

        // ---- S = Q K^T (bf16x3) ----
        float sacc[8][4];
#pragma unroll
        for (int j = 0; j < 8; j++)
#pragma unroll
            for (int e = 0; e < 4; e++) sacc[j][e] = 0.f;

#pragma unroll
        for (int ks = 0; ks < 4; ks++) {
            const uint32_t ks32 = ks * 32;
            uint32_t aqh[4], aql[4];
            ldsm4(aqh, sQh + aoff + ((ks32 + gA) ^ aswz));
            ldsm4(aql, sQl + aoff + ((ks32 + gA) ^ aswz));
#pragma unroll
            for (int jb = 0; jb < 4; jb++) {
                uint32_t roff = (jb * 16 + rowB_) * 128 + ((ks32 + gB) ^ bswz);
                uint32_t kh4[4], kl4[4];
                ldsm4(kh4, sKh + roff);
                ldsm4(kl4, sKl + roff);
                mma16816(sacc[2 * jb + 0], aqh, &kh4[0]);
                mma16816(sacc[2 * jb + 1], aqh, &kh4[2]);
                mma16816(sacc[2 * jb + 0], aqh, &kl4[0]);
                mma16816(sacc[2 * jb + 1], aqh, &kl4[2]);
                mma16816(sacc[2 * jb + 0], aql, &kh4[0]);
                mma16816(sacc[2 * jb + 1], aql, &kh4[2]);
            }
        }

        // ---- causal mask ----
        if ((kt + 1) * 64 - 1 > q0 + wm) {
            const int rb = q0 + wm + (lane >> 2);
            const int cb = kt * 64 + (lane & 3) * 2;
#pragma unroll
            for (int t = 0; t < 8; t++) {
                int c = cb + t * 8;
                if (c     > rb)     sacc[t][0] = -1e30f;
                if (c + 1 > rb)     sacc[t][1] = -1e30f;
                if (c     > rb + 8) sacc[t][2] = -1e30f;
                if (c + 1 > rb + 8) sacc[t][3] = -1e30f;
            }
        }

        // ---- online softmax (rows lane>>2 and +8) ----
        {
            float mx0 = -1e30f, mx1 = -1e30f;
#pragma unroll
            for (int t = 0; t < 8; t++) {
                mx0 = fmaxf(mx0, fmaxf(sacc[t][0], sacc[t][1]));
                mx1 = fmaxf(mx1, fmaxf(sacc[t][2], sacc[t][3]));
            }
            mx0 = fmaxf(mx0, __shfl_xor_sync(0xffffffffu, mx0, 1));
            mx0 = fmaxf(mx0, __shfl_xor_sync(0xffffffffu, mx0, 2));
            mx1 = fmaxf(mx1, __shfl_xor_sync(0xffffffffu, mx1, 1));
            mx1 = fmaxf(mx1, __shfl_xor_sync(0xffffffffu, mx1, 2));
            float mn0 = fmaxf(m0, mx0), mn1 = fmaxf(m1, mx1);
            float a0 = __expf(m0 - mn0), a1 = __expf(m1 - mn1);
            m0 = mn0; m1 = mn1;
            float ls0 = 0.f, ls1 = 0.f;
#pragma unroll
            for (int t = 0; t < 8; t++) {
                sacc[t][0] = __expf(sacc[t][0] - mn0);
                sacc[t][1] = __expf(sacc[t][1] - mn0);
                sacc[t][2] = __expf(sacc[t][2] - mn1);
                sacc[t][3] = __expf(sacc[t][3] - mn1);
                ls0 += sacc[t][0] + sacc[t][1];
                ls1 += sacc[t][2] + sacc[t][3];
            }
            ls0 += __shfl_xor_sync(0xffffffffu, ls0, 1);
            ls0 += __shfl_xor_sync(0xffffffffu, ls0, 2);
            ls1 += __shfl_xor_sync(0xffffffffu, ls1, 1);
            ls1 += __shfl_xor_sync(0xffffffffu, ls1, 2);
            l0 = l0 * a0 + ls0;
            l1 = l1 * a1 + ls1;
#pragma unroll
            for (int j = 0; j < 8; j++) {
                oacc[j][0] *= a0; oacc[j][1] *= a0;
                oacc[j][2] *= a1; oacc[j][3] *= a1;
            }
        }

        // ---- O += P V (bf16x3, P from registers) ----
#pragma unroll
        for (int ks = 0; ks < 4; ks++) {
            uint32_t ah[4], al[4];
            ah[0] = packf(sacc[2*ks][0],   sacc[2*ks][1]);
            ah[1] = packf(sacc[2*ks][2],   sacc[2*ks][3]);
            ah[2] = packf(sacc[2*ks+1][0], sacc[2*ks+1][1]);
            ah[3] = packf(sacc[2*ks+1][2], sacc[2*ks+1][3]);
#pragma unroll
            for (int r = 0; r < 4; r++) {
                float flo = __uint_as_float(ah[r] << 16);
                float fhi = __uint_as_float(ah[r] & 0xffff0000u);
                float s0 = sacc[2*ks + (r >> 1)][(r & 1) * 2 + 0];
                float s1 = sacc[2*ks + (r >> 1)][(r & 1) * 2 + 1];
                al[r] = packf(s0 - flo, s1 - fhi);
            }
            const uint32_t vrow = (ks * 16 + rowV_) * 128;
#pragma unroll
            for (int jb = 0; jb < 4; jb++) {
                uint32_t voff = vrow + ((jb * 32 + gV) ^ vswz);
                uint32_t vh4[4], vl4[4];
                ldsm4t(vh4, sVh + voff);
                ldsm4t(vl4, sVl + voff);
                mma16816(oacc[2 * jb + 0], ah, &vh4[0]);
                mma16816(oacc[2 * jb + 1], ah, &vh4[2]);
                mma16816(oacc[2 * jb + 0], ah, &vl4[0]);
                mma16816(oacc[2 * jb + 1], ah, &vl4[2]);
                mma16816(oacc[2 * jb + 0], al, &vh4[0]);
                mma16816(oacc[2 * jb + 1], al, &vh4[2]);
            }
        }
    }

    // ---- epilogue: normalize, split to bf16 hi/lo, write [b,t,h*64+d] ----
    {
        const int b = bh >> 4, h = bh & (NH - 1);
        const float i0 = 1.f / l0, i1 = 1.f / l1;
        const int t0 = q0 + wm + (lane >> 2);
        const int c0 = h * ND + (lane & 3) * 2;
#pragma unroll
        for (int j = 0; j < 8; j++) {
            float v0 = oacc[j][0] * i0, v1 = oacc[j][1] * i0;
            float v2 = oacc[j][2] * i1, v3 = oacc[j][3] * i1;
            uint32_t ph0 = packf(v0, v1), ph1 = packf(v2, v3);
            uint32_t pl0 = packf(v0 - __uint_as_float(ph0 << 16),
                                 v1 - __uint_as_float(ph0 & 0xffff0000u));
            uint32_t pl1 = packf(v2 - __uint_as_float(ph1 << 16),
                                 v3 - __uint_as_float(ph1 & 0xffff0000u));
            size_t o0 = (size_t)(b * NT + t0) * NC + c0 + j * 8;
            size_t o1 = (size_t)(b * NT + t0 + 8) * NC + c0 + j * 8;
            *(uint32_t*)(Yh_ + o0) = ph0;
            *(uint32_t*)(Yl_ + o0) = pl0;
            *(uint32_t*)(Yh_ + o1) = ph1;
            *(uint32_t*)(Yl_ + o1) = pl1;
        }
    }
}

// ---------------------------------------------------------------------------
extern "C" void kernel_launch(void* const* d_in, const int* in_sizes, int n_in,
                              void* d_out, int out_size)
{
    const float* x  = (const float*)d_in[0];
    const float* Wa = (const float*)d_in[1];
    const float* Wp = (const float*)d_in[2];
    float* out = (float*)d_out;

    float* qkv;
    __nv_bfloat16 *xh, *xl, *yh, *yl, *wah, *wal, *wph, *wpl;
    __nv_bfloat16 *qh, *ql, *kh, *kl, *vh, *vl;
    cudaGetSymbolAddress((void**)&qkv, g_qkv);
    cudaGetSymbolAddress((void**)&xh,  g_xh);
    cudaGetSymbolAddress((void**)&xl,  g_xl);
    cudaGetSymbolAddress((void**)&yh,  g_yh);
    cudaGetSymbolAddress((void**)&yl,  g_yl);
    cudaGetSymbolAddress((void**)&wah, g_wah);
    cudaGetSymbolAddress((void**)&wal, g_wal);
    cudaGetSymbolAddress((void**)&wph, g_wph);
    cudaGetSymbolAddress((void**)&wpl, g_wpl);
    cudaGetSymbolAddress((void**)&qh,  g_qh);
    cudaGetSymbolAddress((void**)&ql,  g_ql);
    cudaGetSymbolAddress((void**)&kh,  g_kh);
    cudaGetSymbolAddress((void**)&kl,  g_kl);
    cudaGetSymbolAddress((void**)&vh,  g_vh);
    cudaGetSymbolAddress((void**)&vl,  g_vl);

    const int gemm_smem = 65536;
    cudaFuncSetAttribute(gemm_mma, cudaFuncAttributeMaxDynamicSharedMemorySize, gemm_smem);
    const int flash_smem = 65536;
    cudaFuncSetAttribute(flash_mma, cudaFuncAttributeMaxDynamicSharedMemorySize, flash_smem);

    // 0) input splits / weight transposes
    cvt_split<<<(NM * NC) / 1024, 256>>>(x, xh, xl);
    wt_split<<<dim3(3 * NC / 32, NC / 32), dim3(32, 8)>>>(Wa, wah, wal, NC, 3 * NC);
    wt_split<<<dim3(NC / 32, NC / 32), dim3(32, 8)>>>(Wp, wph, wpl, NC, NC);

    // 1) QKV = x @ W_attn
    gemm_mma<<<dim3(3 * NC / 128, NM / 128), 256, gemm_smem>>>(
        xh, xl, wah, wal, qkv, NM, 3 * NC, NC);

    // 2) RoPE + split to bf16 hi/lo heads
    rope_split<<<(NBH * NT * ND) / 256, 256>>>(qkv);

    // 3) Flash attention (causal) on tensor cores -> yh/yl
    flash_mma<<<dim3(NT / 128, NBH), 256, flash_smem>>>(
        qh, ql, kh, kl, vh, vl, yh, yl);

    // 4) out = y @ W_proj
    gemm_mma<<<dim3(NC / 128, NM / 128), 256, gemm_smem>>>(
        yh, yl, wph, wpl, out, NM, NC, NC);
}

// round 9
// speedup vs baseline: 6.2303x; 1.0398x over previous
#include <cuda_runtime.h>
#include <cuda_bf16.h>
#include <math.h>
#include <stdint.h>

#define NB 2
#define NT 2048
#define NC 1024
#define NH 16
#define ND 64
#define NBH (NB*NH)
#define NM (NB*NT)   // 4096 rows

// ---------------------------------------------------------------------------
// Scratch (static device allocations)
// ---------------------------------------------------------------------------
__device__ float g_qkv[(size_t)NM * 3 * NC];            // [4096, 3072]

__device__ __nv_bfloat16 g_xh[(size_t)NM * NC];         // x hi/lo
__device__ __nv_bfloat16 g_xl[(size_t)NM * NC];
__device__ __nv_bfloat16 g_yh[(size_t)NM * NC];         // attn out hi/lo
__device__ __nv_bfloat16 g_yl[(size_t)NM * NC];
__device__ __nv_bfloat16 g_wah[(size_t)(3*NC) * NC];    // Wa^T hi/lo [3072][1024]
__device__ __nv_bfloat16 g_wal[(size_t)(3*NC) * NC];
__device__ __nv_bfloat16 g_wph[(size_t)NC * NC];        // Wp^T hi/lo
__device__ __nv_bfloat16 g_wpl[(size_t)NC * NC];

__device__ __nv_bfloat16 g_qh[(size_t)NBH * NT * ND];   // RoPE'd Q*scale hi/lo
__device__ __nv_bfloat16 g_ql[(size_t)NBH * NT * ND];
__device__ __nv_bfloat16 g_kh[(size_t)NBH * NT * ND];
__device__ __nv_bfloat16 g_kl[(size_t)NBH * NT * ND];
__device__ __nv_bfloat16 g_vh[(size_t)NBH * NT * ND];
__device__ __nv_bfloat16 g_vl[(size_t)NBH * NT * ND];

// ---------------------------------------------------------------------------
__device__ __forceinline__ uint32_t smem_u32(const void* p) {
    uint32_t a;
    asm("{ .reg .u64 t; cvta.to.shared.u64 t, %1; cvt.u32.u64 %0, t; }"
        : "=r"(a) : "l"(p));
    return a;
}
#define SWZ(o)   ((o) ^ (((o) >> 3) & 0x70))   // SW128 (128B rows)
#define SWZ64(o) ((o) ^ (((o) >> 3) & 0x30))   // SW64  (64B rows)

__device__ __forceinline__ void cpa16(uint32_t dst, const void* src) {
    asm volatile("cp.async.cg.shared.global [%0], [%1], 16;"
                 :: "r"(dst), "l"(src) : "memory");
}
#define CP_COMMIT() asm volatile("cp.async.commit_group;" ::: "memory")
#define CP_WAIT1()  asm volatile("cp.async.wait_group 1;" ::: "memory")
#define CP_WAIT0()  asm volatile("cp.async.wait_group 0;" ::: "memory")

__device__ __forceinline__ void ldsm4(uint32_t* r, uint32_t addr) {
    asm volatile("ldmatrix.sync.aligned.m8n8.x4.shared.b16 {%0,%1,%2,%3}, [%4];"
                 : "=r"(r[0]), "=r"(r[1]), "=r"(r[2]), "=r"(r[3]) : "r"(addr));
}
__device__ __forceinline__ void ldsm4t(uint32_t* r, uint32_t addr) {
    asm volatile("ldmatrix.sync.aligned.m8n8.x4.trans.shared.b16 {%0,%1,%2,%3}, [%4];"
                 : "=r"(r[0]), "=r"(r[1]), "=r"(r[2]), "=r"(r[3]) : "r"(addr));
}
__device__ __forceinline__ void mma16816(float* d, const uint32_t* a, const uint32_t* b) {
    asm volatile(
        "mma.sync.aligned.m16n8k16.row.col.f32.bf16.bf16.f32 "
        "{%0,%1,%2,%3}, {%4,%5,%6,%7}, {%8,%9}, {%0,%1,%2,%3};"
        : "+f"(d[0]), "+f"(d[1]), "+f"(d[2]), "+f"(d[3])
        : "r"(a[0]), "r"(a[1]), "r"(a[2]), "r"(a[3]), "r"(b[0]), "r"(b[1]));
}
__device__ __forceinline__ uint32_t packf(float lo, float hi) {
    uint32_t d;
    asm("cvt.rn.bf16x2.f32 %0, %1, %2;" : "=r"(d) : "f"(hi), "f"(lo));
    return d;
}

// ---------------------------------------------------------------------------
// Elementwise fp32 -> bf16 hi/lo split
// ---------------------------------------------------------------------------
__global__ void cvt_split(const float* __restrict__ in,
                          __nv_bfloat16* __restrict__ h,
                          __nv_bfloat16* __restrict__ l) {
    int i = (blockIdx.x * blockDim.x + threadIdx.x) * 4;
    float4 a = *(const float4*)(in + i);
    float v[4] = {a.x, a.y, a.z, a.w};
    __nv_bfloat16 hh[4], ll[4];
#pragma unroll
    for (int j = 0; j < 4; j++) {
        hh[j] = __float2bfloat16(v[j]);
        ll[j] = __float2bfloat16(v[j] - __bfloat162float(hh[j]));
    }
    *(__nv_bfloat162*)(h + i)     = *(__nv_bfloat162*)&hh[0];
    *(__nv_bfloat162*)(h + i + 2) = *(__nv_bfloat162*)&hh[2];
    *(__nv_bfloat162*)(l + i)     = *(__nv_bfloat162*)&ll[0];
    *(__nv_bfloat162*)(l + i + 2) = *(__nv_bfloat162*)&ll[2];
}

// ---------------------------------------------------------------------------
// W [K][N] fp32 -> W^T hi/lo [N][K] bf16
// ---------------------------------------------------------------------------
__global__ void wt_split(const float* __restrict__ W,
                         __nv_bfloat16* __restrict__ Th,
                         __nv_bfloat16* __restrict__ Tl, int K, int N) {
    __shared__ float t[32][33];
    int n0 = blockIdx.x * 32, k0 = blockIdx.y * 32;
    int tx = threadIdx.x, ty0 = threadIdx.y;
#pragma unroll
    for (int i = 0; i < 4; i++) {
        int ty = ty0 + i * 8;
        t[ty][tx] = W[(size_t)(k0 + ty) * N + n0 + tx];
    }
    __syncthreads();
#pragma unroll
    for (int i = 0; i < 4; i++) {
        int ty = ty0 + i * 8;
        float a = t[tx][ty];
        __nv_bfloat16 h = __float2bfloat16(a);
        __nv_bfloat16 l = __float2bfloat16(a - __bfloat162float(h));
        Th[(size_t)(n0 + ty) * K + k0 + tx] = h;
        Tl[(size_t)(n0 + ty) * K + k0 + tx] = l;
    }
}

// ---------------------------------------------------------------------------
// HMMA bf16x3 GEMM, cp.async double-buffered. K-chunk 32, 2 stages of
// 4 tiles x 8KB (128 rows x 32 bf16, 64B rows, SW64). CTA 128x128, 8 warps.
// ---------------------------------------------------------------------------
__global__ __launch_bounds__(256, 2) void gemm_mma(
    const __nv_bfloat16* __restrict__ Ah, const __nv_bfloat16* __restrict__ Al,
    const __nv_bfloat16* __restrict__ Bh, const __nv_bfloat16* __restrict__ Bl,
    float* __restrict__ C, int M, int N, int K) {
    extern __shared__ char smem[];
    const uint32_t sb = smem_u32(smem);   // stage s at sb + s*32768
                                          // tiles: Ah@0 Al@8192 Bh@16384 Bl@24576
    const int tid = threadIdx.x, wid = tid >> 5, lane = tid & 31;
    const int m0 = blockIdx.y * 128, n0 = blockIdx.x * 128;
    const int wm0 = (wid >> 2) * 64, wn0 = (wid & 3) * 32;

    const __nv_bfloat16* bA0 = Ah + (size_t)m0 * K;
    const __nv_bfloat16* bA1 = Al + (size_t)m0 * K;
    const __nv_bfloat16* bB0 = Bh + (size_t)n0 * K;
    const __nv_bfloat16* bB1 = Bl + (size_t)n0 * K;

    // fragment addresses (64B rows, SW64)
    uint32_t a_r[4], a_z[4];
#pragma unroll
    for (int i = 0; i < 4; i++) {
        int row = wm0 + 16 * i + (lane & 15);
        a_r[i] = row * 64;
        a_z[i] = (row & 6) << 3;
    }
    const uint32_t gA = (lane >> 4) * 16;
    uint32_t b_r[2], b_z[2];
#pragma unroll
    for (int j = 0; j < 2; j++) {
        int row = wn0 + 16 * j + (lane & 7) + ((lane >> 4) << 3);
        b_r[j] = row * 64;
        b_z[j] = (row & 6) << 3;
    }
    const uint32_t gB = ((lane >> 3) & 1) * 16;

    float acc[4][4][4];
#pragma unroll
    for (int i = 0; i < 4; i++)
#pragma unroll
        for (int j = 0; j < 4; j++)
#pragma unroll
            for (int q = 0; q < 4; q++) acc[i][j][q] = 0.f;

    // prefetch issue: 8 x 16B per thread (2 per tile)
#define G_ISSUE(cc, ss)                                                        \
    do {                                                                       \
        const int k0_ = (cc) * 32;                                             \
        const uint32_t stb_ = sb + (ss) * 32768;                               \
        _Pragma("unroll")                                                      \
        for (int i_ = 0; i_ < 8; i_++) {                                       \
            const __nv_bfloat16* base_ =                                       \
                (i_ >> 1) == 0 ? bA0 : (i_ >> 1) == 1 ? bA1                    \
              : (i_ >> 1) == 2 ? bB0 : bB1;                                    \
            int w_ = tid + (i_ & 1) * 256;                                     \
            int r_ = w_ >> 2, c4_ = w_ & 3;                                    \
            cpa16(stb_ + (i_ >> 1) * 8192 + SWZ64(r_ * 64 + c4_ * 16),         \
                  base_ + (size_t)r_ * K + k0_ + c4_ * 8);                     \
        }                                                                      \
        CP_COMMIT();                                                           \
    } while (0)

    const int nch = K / 32;
    G_ISSUE(0, 0);
    for (int c = 0; c < nch; c++) {
        const int s = c & 1;
        if (c + 1 < nch) { G_ISSUE(c + 1, s ^ 1); CP_WAIT1(); }
        else             { CP_WAIT0(); }
        __syncthreads();

        const uint32_t stb = sb + s * 32768;
#pragma unroll
        for (int ks = 0; ks < 2; ks++) {
            const uint32_t off = ks * 32;
            uint32_t af[4][4], bh2[2][4], bl2[2][4];
#pragma unroll
            for (int i = 0; i < 4; i++)
                ldsm4(af[i], stb + a_r[i] + ((off + gA) ^ a_z[i]));
#pragma unroll
            for (int j = 0; j < 2; j++) {
                ldsm4(bh2[j], stb + 16384 + b_r[j] + ((off + gB) ^ b_z[j]));
                ldsm4(bl2[j], stb + 24576 + b_r[j] + ((off + gB) ^ b_z[j]));
            }
#pragma unroll
            for (int i = 0; i < 4; i++)
#pragma unroll
                for (int j = 0; j < 2; j++) {
                    mma16816(acc[i][j * 2 + 0], af[i], &bh2[j][0]);
                    mma16816(acc[i][j * 2 + 1], af[i], &bh2[j][2]);
                }
#pragma unroll
            for (int i = 0; i < 4; i++)
#pragma unroll
                for (int j = 0; j < 2; j++) {
                    mma16816(acc[i][j * 2 + 0], af[i], &bl2[j][0]);
                    mma16816(acc[i][j * 2 + 1], af[i], &bl2[j][2]);
                }
#pragma unroll
            for (int i = 0; i < 4; i++)
                ldsm4(af[i], stb + 8192 + a_r[i] + ((off + gA) ^ a_z[i]));
#pragma unroll
            for (int i = 0; i < 4; i++)
#pragma unroll
                for (int j = 0; j < 2; j++) {
                    mma16816(acc[i][j * 2 + 0], af[i], &bh2[j][0]);
                    mma16816(acc[i][j * 2 + 1], af[i], &bh2[j][2]);
                }
        }
        __syncthreads();
    }
#undef G_ISSUE

    const int er = lane >> 2, ec = (lane & 3) * 2;
#pragma unroll
    for (int i = 0; i < 4; i++) {
        int r = m0 + wm0 + 16 * i + er;
#pragma unroll
        for (int j = 0; j < 4; j++) {
            int col = n0 + wn0 + 8 * j + ec;
            *(float2*)(C + (size_t)r * N + col)       = make_float2(acc[i][j][0], acc[i][j][1]);
            *(float2*)(C + (size_t)(r + 8) * N + col) = make_float2(acc[i][j][2], acc[i][j][3]);
        }
    }
}

// ---------------------------------------------------------------------------
// RoPE + head split; emit bf16 hi/lo Q(*0.125)/K/V in [BH][T][64]
// ---------------------------------------------------------------------------
__global__ void rope_split(const float* __restrict__ qkv)
{
    int idx = blockIdx.x * blockDim.x + threadIdx.x;
    int d  = idx & (ND - 1);
    int t  = (idx >> 6) & (NT - 1);
    int bh = idx >> 17;
    int b = bh >> 4, h = bh & (NH - 1);
    const float* base = qkv + (size_t)(b * NT + t) * (3 * NC);
    int col  = h * ND + d;
    int colm = h * ND + ((d + ND - 1) & (ND - 1));
    float qd = base[col],      qm = base[colm];
    float kd = base[NC + col], km = base[NC + colm];
    float vd = base[2 * NC + col];

    int fi = d & 31;
    float inv = expf(-(float)fi * (9.210340371976184f / 32.0f));
    float ang = (float)t * inv;
    float sn, cs;
    sincosf(ang, &sn, &cs);

    float qv = (qd * cs + qm * sn) * 0.125f;
    float kv = kd * cs + km * sn;

    __nv_bfloat16 hh;
    hh = __float2bfloat16(qv);
    g_qh[idx] = hh; g_ql[idx] = __float2bfloat16(qv - __bfloat162float(hh));
    hh = __float2bfloat16(kv);
    g_kh[idx] = hh; g_kl[idx] = __float2bfloat16(kv - __bfloat162float(hh));
    hh = __float2bfloat16(vd);
    g_vh[idx] = hh; g_vl[idx] = __float2bfloat16(vd - __bfloat162float(hh));
}

// ---------------------------------------------------------------------------
// Flash attention on HMMA, cp.async double-buffered K/V tiles.
// smem: Q hi/lo 32KB @ sb; KV stages 32KB each @ sb+32768 + s*32768.
// ---------------------------------------------------------------------------
__global__ __launch_bounds__(256, 2) void flash_mma(
    const __nv_bfloat16* __restrict__ Qh_, const __nv_bfloat16* __restrict__ Ql_,
    const __nv_bfloat16* __restrict__ Kh_, const __nv_bfloat16* __restrict__ Kl_,
    const __nv_bfloat16* __restrict__ Vh_, const __nv_bfloat16* __restrict__ Vl_,
    __nv_bfloat16* __restrict__ Yh_, __nv_bfloat16* __restrict__ Yl_)
{
    extern __shared__ char smem[];
    const uint32_t sb = smem_u32(smem);
    const uint32_t sQh = sb, sQl = sb + 16384;

    const int bh = blockIdx.y, qi = blockIdx.x, q0 = qi * 128;
    const int tid = threadIdx.x, wid = tid >> 5, lane = tid & 31;
    const int wm = wid * 16;
    const size_t gbase = (size_t)bh * NT * ND;

    const __nv_bfloat16* pKh = Kh_ + gbase;
    const __nv_bfloat16* pKl = Kl_ + gbase;
    const __nv_bfloat16* pVh = Vh_ + gbase;
    const __nv_bfloat16* pVl = Vl_ + gbase;

    // ---- load Q hi/lo (128x64, SW128) ----
    {
        const __nv_bfloat16* s0 = Qh_ + gbase + (size_t)q0 * ND;
        const __nv_bfloat16* s1 = Ql_ + gbase + (size_t)q0 * ND;
#pragma unroll
        for (int i = 0; i < 4; i++) {
            int idx = tid + i * 256;
            int r = idx >> 3, c8 = idx & 7;
            uint32_t off = SWZ(r * 128 + c8 * 16);
            uint4 v = *(const uint4*)(s0 + (size_t)r * ND + c8 * 8);
            asm volatile("st.shared.v4.b32 [%0], {%1,%2,%3,%4};"
                         :: "r"(sQh + off), "r"(v.x), "r"(v.y), "r"(v.z), "r"(v.w));
            uint4 w = *(const uint4*)(s1 + (size_t)r * ND + c8 * 8);
            asm volatile("st.shared.v4.b32 [%0], {%1,%2,%3,%4};"
                         :: "r"(sQl + off), "r"(w.x), "r"(w.y), "r"(w.z), "r"(w.w));
        }
    }

    // KV prefetch: tiles Kh@0 Kl@8192 Vh@16384 Vl@24576 within stage
#define F_ISSUE(kt_, ss)                                                       \
    do {                                                                       \
        const size_t ko_ = (size_t)(kt_) * 64 * ND;                            \
        const uint32_t kvb_ = sb + 32768 + (ss) * 32768;                       \
        _Pragma("unroll")                                                      \
        for (int i_ = 0; i_ < 8; i_++) {                                       \
            const __nv_bfloat16* base_ =                                       \
                (i_ >> 1) == 0 ? pKh : (i_ >> 1) == 1 ? pKl                    \
              : (i_ >> 1) == 2 ? pVh : pVl;                                    \
            int w_ = tid + (i_ & 1) * 256;                                     \
            int r_ = w_ >> 3, c8_ = w_ & 7;                                    \
            cpa16(kvb_ + (i_ >> 1) * 8192 + SWZ(r_ * 128 + c8_ * 16),          \
                  base_ + ko_ + (size_t)r_ * ND + c8_ * 8);                    \
        }                                                                      \
        CP_COMMIT();                                                           \
    } while (0)

    // per-lane fragment address components
    const int rowA = wm + (lane & 15);
    const uint32_t aoff = rowA * 128, aswz = (rowA & 7) * 16;
    const uint32_t gA = (lane >> 4) * 16;
    const int rowB_ = (lane & 7) + ((lane >> 4) << 3);        // K (non-trans)
    const uint32_t bswz = (rowB_ & 7) * 16;
    const uint32_t gB = ((lane >> 3) & 1) * 16;
    const int rowV_ = ((lane >> 3) & 1) * 8 + (lane & 7);     // V (trans)
    const uint32_t vswz = (lane & 7) * 16;
    const uint32_t gV = (lane >> 4) * 16;

    float m0 = -1e30f, m1 = -1e30f, l0 = 0.f, l1 = 0.f;
    float oacc[8][4];
#pragma unroll
    for (int j = 0; j < 8; j++)
#pragma unroll
        for (int e = 0; e < 4; e++) oacc[j][e] = 0.f;

    const int nkt = 2 * qi + 2;
    F_ISSUE(0, 0);
    for (int kt = 0; kt < nkt; kt++) {
        const int s = kt & 1;
        if (kt + 1 < nkt) { F_ISSUE(kt + 1, s ^ 1); CP_WAIT1(); }
        else              { CP_WAIT0(); }
        __syncthreads();

        const uint32_t kvb = sb + 32768 + s * 32768;
        const uint32_t sKh = kvb, sKl = kvb + 8192;
        const uint32_t sVh = kvb + 16384, sVl = kvb + 24576;

        if (kt * 64 <= q0 + wm + 15) {   // not fully masked for this warp
            // ---- S = Q K^T (bf16x3) ----
            float sacc[8][4];
#pragma unroll
            for (int j = 0; j < 8; j++)
#pragma unroll
                for (int e = 0; e < 4; e++) sacc[j][e] = 0.f;

#pragma unroll
            for (int ks = 0; ks < 4; ks++) {
                const uint32_t ks32 = ks * 32;
                uint32_t aqh[4], aql[4];
                ldsm4(aqh, sQh + aoff + ((ks32 + gA) ^ aswz));
                ldsm4(aql, sQl + aoff + ((ks32 + gA) ^ aswz));
#pragma unroll
                for (int jb = 0; jb < 4; jb++) {
                    uint32_t roff = (jb * 16 + rowB_) * 128 + ((ks32 + gB) ^ bswz);
                    uint32_t kh4[4], kl4[4];
                    ldsm4(kh4, sKh + roff);
                    ldsm4(kl4, sKl + roff);
                    mma16816(sacc[2 * jb + 0], aqh, &kh4[0]);
                    mma16816(sacc[2 * jb + 1], aqh, &kh4[2]);
                    mma16816(sacc[2 * jb + 0], aqh, &kl4[0]);
                    mma16816(sacc[2 * jb + 1], aqh, &kl4[2]);
                    mma16816(sacc[2 * jb + 0], aql, &kh4[0]);
                    mma16816(sacc[2 * jb + 1], aql, &kh4[2]);
                }
            }

            // ---- causal mask ----
            if ((kt + 1) * 64 - 1 > q0 + wm) {
                const int rb = q0 + wm + (lane >> 2);
                const int cb = kt * 64 + (lane & 3) * 2;
#pragma unroll
                for (int t = 0; t < 8; t++) {
                    int c = cb + t * 8;
                    if (c     > rb)     sacc[t][0] = -1e30f;
                    if (c + 1 > rb)     sacc[t][1] = -1e30f;
                    if (c     > rb + 8) sacc[t][2] = -1e30f;
                    if (c + 1 > rb + 8) sacc[t][3] = -1e30f;
                }
            }

            // ---- online softmax ----
            {
                float mx0 = -1e30f, mx1 = -1e30f;
#pragma unroll
                for (int t = 0; t < 8; t++) {
                    mx0 = fmaxf(mx0, fmaxf(sacc[t][0], sacc[t][1]));
                    mx1 = fmaxf(mx1, fmaxf(sacc[t][2], sacc[t][3]));
                }
                mx0 = fmaxf(mx0, __shfl_xor_sync(0xffffffffu, mx0, 1));
                mx0 = fmaxf(mx0, __shfl_xor_sync(0xffffffffu, mx0, 2));
                mx1 = fmaxf(mx1, __shfl_xor_sync(0xffffffffu, mx1, 1));
                mx1 = fmaxf(mx1, __shfl_xor_sync(0xffffffffu, mx1, 2));
                float mn0 = fmaxf(m0, mx0), mn1 = fmaxf(m1, mx1);
                float a0 = __expf(m0 - mn0), a1 = __expf(m1 - mn1);
                m0 = mn0; m1 = mn1;
                float ls0 = 0.f, ls1 = 0.f;
#pragma unroll
                for (int t = 0; t < 8; t++) {
                    sacc[t][0] = __expf(sacc[t][0] - mn0);
                    sacc[t][1] = __expf(sacc[t][1] - mn0);
                    sacc[t][2] = __expf(sacc[t][2] - mn1);
                    sacc[t][3] = __expf(sacc[t][3] - mn1);
                    ls0 += sacc[t][0] + sacc[t][1];
                    ls1 += sacc[t][2] + sacc[t][3];
                }
                ls0 += __shfl_xor_sync(0xffffffffu, ls0, 1);
                ls0 += __shfl_xor_sync(0xffffffffu, ls0, 2);
                ls1 += __shfl_xor_sync(0xffffffffu, ls1, 1);
                ls1 += __shfl_xor_sync(0xffffffffu, ls1, 2);
                l0 = l0 * a0 + ls0;
                l1 = l1 * a1 + ls1;
#pragma unroll
                for (int j = 0; j < 8; j++) {
                    oacc[j][0] *= a0; oacc[j][1] *= a0;
                    oacc[j][2] *= a1; oacc[j][3] *= a1;
                }
            }

            // ---- O += P V (bf16x3, P from registers) ----
#pragma unroll
            for (int ks = 0; ks < 4; ks++) {
                uint32_t ah[4], al[4];
                ah[0] = packf(sacc[2*ks][0],   sacc[2*ks][1]);
                ah[1] = packf(sacc[2*ks][2],   sacc[2*ks][3]);
                ah[2] = packf(sacc[2*ks+1][0], sacc[2*ks+1][1]);
                ah[3] = packf(sacc[2*ks+1][2], sacc[2*ks+1][3]);
#pragma unroll
                for (int r = 0; r < 4; r++) {
                    float flo = __uint_as_float(ah[r] << 16);
                    float fhi = __uint_as_float(ah[r] & 0xffff0000u);
                    float s0 = sacc[2*ks + (r >> 1)][(r & 1) * 2 + 0];
                    float s1 = sacc[2*ks + (r >> 1)][(r & 1) * 2 + 1];
                    al[r] = packf(s0 - flo, s1 - fhi);
                }
                const uint32_t vrow = (ks * 16 + rowV_) * 128;
#pragma unroll
                for (int jb = 0; jb < 4; jb++) {
                    uint32_t voff = vrow + ((jb * 32 + gV) ^ vswz);
                    uint32_t vh4[4], vl4[4];
                    ldsm4t(vh4, sVh + voff);
                    ldsm4t(vl4, sVl + voff);
                    mma16816(oacc[2 * jb + 0], ah, &vh4[0]);
                    mma16816(oacc[2 * jb + 1], ah, &vh4[2]);
                    mma16816(oacc[2 * jb + 0], ah, &vl4[0]);
                    mma16816(oacc[2 * jb + 1], ah, &vl4[2]);
                    mma16816(oacc[2 * jb + 0], al, &vh4[0]);
                    mma16816(oacc[2 * jb + 1], al, &vh4[2]);
                }
            }
        }
        __syncthreads();   // stage reusable for prefetch next iteration
    }
#undef F_ISSUE

    // ---- epilogue ----
    {
        const int b = bh >> 4, h = bh & (NH - 1);
        const float i0 = 1.f / l0, i1 = 1.f / l1;
        const int t0 = q0 + wm + (lane >> 2);
        const int c0 = h * ND + (lane & 3) * 2;
#pragma unroll
        for (int j = 0; j < 8; j++) {
            float v0 = oacc[j][0] * i0, v1 = oacc[j][1] * i0;
            float v2 = oacc[j][2] * i1, v3 = oacc[j][3] * i1;
            uint32_t ph0 = packf(v0, v1), ph1 = packf(v2, v3);
            uint32_t pl0 = packf(v0 - __uint_as_float(ph0 << 16),
                                 v1 - __uint_as_float(ph0 & 0xffff0000u));
            uint32_t pl1 = packf(v2 - __uint_as_float(ph1 << 16),
                                 v3 - __uint_as_float(ph1 & 0xffff0000u));
            size_t o0 = (size_t)(b * NT + t0) * NC + c0 + j * 8;
            size_t o1 = (size_t)(b * NT + t0 + 8) * NC + c0 + j * 8;
            *(uint32_t*)(Yh_ + o0) = ph0;
            *(uint32_t*)(Yl_ + o0) = pl0;
            *(uint32_t*)(Yh_ + o1) = ph1;
            *(uint32_t*)(Yl_ + o1) = pl1;
        }
    }
}

// ---------------------------------------------------------------------------
extern "C" void kernel_launch(void* const* d_in, const int* in_sizes, int n_in,
                              void* d_out, int out_size)
{
    const float* x  = (const float*)d_in[0];
    const float* Wa = (const float*)d_in[1];
    const float* Wp = (const float*)d_in[2];
    float* out = (float*)d_out;

    float* qkv;
    __nv_bfloat16 *xh, *xl, *yh, *yl, *wah, *wal, *wph, *wpl;
    __nv_bfloat16 *qh, *ql, *kh, *kl, *vh, *vl;
    cudaGetSymbolAddress((void**)&qkv, g_qkv);
    cudaGetSymbolAddress((void**)&xh,  g_xh);
    cudaGetSymbolAddress((void**)&xl,  g_xl);
    cudaGetSymbolAddress((void**)&yh,  g_yh);
    cudaGetSymbolAddress((void**)&yl,  g_yl);
    cudaGetSymbolAddress((void**)&wah, g_wah);
    cudaGetSymbolAddress((void**)&wal, g_wal);
    cudaGetSymbolAddress((void**)&wph, g_wph);
    cudaGetSymbolAddress((void**)&wpl, g_wpl);
    cudaGetSymbolAddress((void**)&qh,  g_qh);
    cudaGetSymbolAddress((void**)&ql,  g_ql);
    cudaGetSymbolAddress((void**)&kh,  g_kh);
    cudaGetSymbolAddress((void**)&kl,  g_kl);
    cudaGetSymbolAddress((void**)&vh,  g_vh);
    cudaGetSymbolAddress((void**)&vl,  g_vl);

    const int gemm_smem = 65536;          // 2 stages x 32KB
    cudaFuncSetAttribute(gemm_mma, cudaFuncAttributeMaxDynamicSharedMemorySize, gemm_smem);
    const int flash_smem = 98304;         // Q 32KB + 2 stages x 32KB
    cudaFuncSetAttribute(flash_mma, cudaFuncAttributeMaxDynamicSharedMemorySize, flash_smem);

    // 0) input splits / weight transposes
    cvt_split<<<(NM * NC) / 1024, 256>>>(x, xh, xl);
    wt_split<<<dim3(3 * NC / 32, NC / 32), dim3(32, 8)>>>(Wa, wah, wal, NC, 3 * NC);
    wt_split<<<dim3(NC / 32, NC / 32), dim3(32, 8)>>>(Wp, wph, wpl, NC, NC);

    // 1) QKV = x @ W_attn
    gemm_mma<<<dim3(3 * NC / 128, NM / 128), 256, gemm_smem>>>(
        xh, xl, wah, wal, qkv, NM, 3 * NC, NC);

    // 2) RoPE + split to bf16 hi/lo heads
    rope_split<<<(NBH * NT * ND) / 256, 256>>>(qkv);

    // 3) Flash attention (causal) on tensor cores -> yh/yl
    flash_mma<<<dim3(NT / 128, NBH), 256, flash_smem>>>(
        qh, ql, kh, kl, vh, vl, yh, yl);

    // 4) out = y @ W_proj
    gemm_mma<<<dim3(NC / 128, NM / 128), 256, gemm_smem>>>(
        yh, yl, wph, wpl, out, NM, NC, NC);
}

// round 10
// speedup vs baseline: 6.3268x; 1.0155x over previous
#include <cuda_runtime.h>
#include <cuda_bf16.h>
#include <math.h>
#include <stdint.h>

#define NB 2
#define NT 2048
#define NC 1024
#define NH 16
#define ND 64
#define NBH (NB*NH)
#define NM (NB*NT)   // 4096 rows

// ---------------------------------------------------------------------------
// Scratch (static device allocations)
// ---------------------------------------------------------------------------
__device__ float g_qkv[(size_t)NM * 3 * NC];            // [4096, 3072]

__device__ __nv_bfloat16 g_xh[(size_t)NM * NC];         // x hi/lo
__device__ __nv_bfloat16 g_xl[(size_t)NM * NC];
__device__ __nv_bfloat16 g_yh[(size_t)NM * NC];         // attn out hi/lo
__device__ __nv_bfloat16 g_yl[(size_t)NM * NC];
__device__ __nv_bfloat16 g_wah[(size_t)(3*NC) * NC];    // Wa^T hi/lo [3072][1024]
__device__ __nv_bfloat16 g_wal[(size_t)(3*NC) * NC];
__device__ __nv_bfloat16 g_wph[(size_t)NC * NC];        // Wp^T hi/lo
__device__ __nv_bfloat16 g_wpl[(size_t)NC * NC];

__device__ __nv_bfloat16 g_qh[(size_t)NBH * NT * ND];   // RoPE'd Q*scale hi/lo
__device__ __nv_bfloat16 g_ql[(size_t)NBH * NT * ND];
__device__ __nv_bfloat16 g_kh[(size_t)NBH * NT * ND];
__device__ __nv_bfloat16 g_kl[(size_t)NBH * NT * ND];
__device__ __nv_bfloat16 g_vh[(size_t)NBH * NT * ND];
__device__ __nv_bfloat16 g_vl[(size_t)NBH * NT * ND];

// ---------------------------------------------------------------------------
__device__ __forceinline__ uint32_t smem_u32(const void* p) {
    uint32_t a;
    asm("{ .reg .u64 t; cvta.to.shared.u64 t, %1; cvt.u32.u64 %0, t; }"
        : "=r"(a) : "l"(p));
    return a;
}
#define SWZ(o)   ((o) ^ (((o) >> 3) & 0x70))   // SW128 (128B rows)
#define SWZ64(o) ((o) ^ (((o) >> 3) & 0x30))   // SW64  (64B rows)

__device__ __forceinline__ void cpa16(uint32_t dst, const void* src) {
    asm volatile("cp.async.cg.shared.global [%0], [%1], 16;"
                 :: "r"(dst), "l"(src) : "memory");
}
#define CP_COMMIT() asm volatile("cp.async.commit_group;" ::: "memory")
#define CP_WAIT2()  asm volatile("cp.async.wait_group 2;" ::: "memory")
#define CP_WAIT1()  asm volatile("cp.async.wait_group 1;" ::: "memory")
#define CP_WAIT0()  asm volatile("cp.async.wait_group 0;" ::: "memory")

__device__ __forceinline__ void ldsm4(uint32_t* r, uint32_t addr) {
    asm volatile("ldmatrix.sync.aligned.m8n8.x4.shared.b16 {%0,%1,%2,%3}, [%4];"
                 : "=r"(r[0]), "=r"(r[1]), "=r"(r[2]), "=r"(r[3]) : "r"(addr));
}
__device__ __forceinline__ void ldsm4t(uint32_t* r, uint32_t addr) {
    asm volatile("ldmatrix.sync.aligned.m8n8.x4.trans.shared.b16 {%0,%1,%2,%3}, [%4];"
                 : "=r"(r[0]), "=r"(r[1]), "=r"(r[2]), "=r"(r[3]) : "r"(addr));
}
__device__ __forceinline__ void mma16816(float* d, const uint32_t* a, const uint32_t* b) {
    asm volatile(
        "mma.sync.aligned.m16n8k16.row.col.f32.bf16.bf16.f32 "
        "{%0,%1,%2,%3}, {%4,%5,%6,%7}, {%8,%9}, {%0,%1,%2,%3};"
        : "+f"(d[0]), "+f"(d[1]), "+f"(d[2]), "+f"(d[3])
        : "r"(a[0]), "r"(a[1]), "r"(a[2]), "r"(a[3]), "r"(b[0]), "r"(b[1]));
}
__device__ __forceinline__ uint32_t packf(float lo, float hi) {
    uint32_t d;
    asm("cvt.rn.bf16x2.f32 %0, %1, %2;" : "=r"(d) : "f"(hi), "f"(lo));
    return d;
}

// ---------------------------------------------------------------------------
// Elementwise fp32 -> bf16 hi/lo split
// ---------------------------------------------------------------------------
__global__ void cvt_split(const float* __restrict__ in,
                          __nv_bfloat16* __restrict__ h,
                          __nv_bfloat16* __restrict__ l) {
    int i = (blockIdx.x * blockDim.x + threadIdx.x) * 4;
    float4 a = *(const float4*)(in + i);
    float v[4] = {a.x, a.y, a.z, a.w};
    __nv_bfloat16 hh[4], ll[4];
#pragma unroll
    for (int j = 0; j < 4; j++) {
        hh[j] = __float2bfloat16(v[j]);
        ll[j] = __float2bfloat16(v[j] - __bfloat162float(hh[j]));
    }
    *(__nv_bfloat162*)(h + i)     = *(__nv_bfloat162*)&hh[0];
    *(__nv_bfloat162*)(h + i + 2) = *(__nv_bfloat162*)&hh[2];
    *(__nv_bfloat162*)(l + i)     = *(__nv_bfloat162*)&ll[0];
    *(__nv_bfloat162*)(l + i + 2) = *(__nv_bfloat162*)&ll[2];
}

// ---------------------------------------------------------------------------
// W [K][N] fp32 -> W^T hi/lo [N][K] bf16
// ---------------------------------------------------------------------------
__global__ void wt_split(const float* __restrict__ W,
                         __nv_bfloat16* __restrict__ Th,
                         __nv_bfloat16* __restrict__ Tl, int K, int N) {
    __shared__ float t[32][33];
    int n0 = blockIdx.x * 32, k0 = blockIdx.y * 32;
    int tx = threadIdx.x, ty0 = threadIdx.y;
#pragma unroll
    for (int i = 0; i < 4; i++) {
        int ty = ty0 + i * 8;
        t[ty][tx] = W[(size_t)(k0 + ty) * N + n0 + tx];
    }
    __syncthreads();
#pragma unroll
    for (int i = 0; i < 4; i++) {
        int ty = ty0 + i * 8;
        float a = t[tx][ty];
        __nv_bfloat16 h = __float2bfloat16(a);
        __nv_bfloat16 l = __float2bfloat16(a - __bfloat162float(h));
        Th[(size_t)(n0 + ty) * K + k0 + tx] = h;
        Tl[(size_t)(n0 + ty) * K + k0 + tx] = l;
    }
}

// ---------------------------------------------------------------------------
// HMMA bf16x3 GEMM, 3-stage cp.async pipeline, ONE barrier per chunk.
// K-chunk 32; stage = 4 tiles x 8KB (128 rows x 32 bf16, SW64). CTA 128x128.
// Per iter: wait(stage c) -> bar -> issue(stage c+2) -> compute(stage c).
// ---------------------------------------------------------------------------
__global__ __launch_bounds__(256, 2) void gemm_mma(
    const __nv_bfloat16* __restrict__ Ah, const __nv_bfloat16* __restrict__ Al,
    const __nv_bfloat16* __restrict__ Bh, const __nv_bfloat16* __restrict__ Bl,
    float* __restrict__ C, int M, int N, int K) {
    extern __shared__ char smem[];
    const uint32_t sb = smem_u32(smem);   // stage s at sb + s*32768
                                          // tiles: Ah@0 Al@8192 Bh@16384 Bl@24576
    const int tid = threadIdx.x, wid = tid >> 5, lane = tid & 31;
    const int m0 = blockIdx.y * 128, n0 = blockIdx.x * 128;
    const int wm0 = (wid >> 2) * 64, wn0 = (wid & 3) * 32;

    const __nv_bfloat16* bA0 = Ah + (size_t)m0 * K;
    const __nv_bfloat16* bA1 = Al + (size_t)m0 * K;
    const __nv_bfloat16* bB0 = Bh + (size_t)n0 * K;
    const __nv_bfloat16* bB1 = Bl + (size_t)n0 * K;

    // fragment addresses (64B rows, SW64)
    uint32_t a_r[4], a_z[4];
#pragma unroll
    for (int i = 0; i < 4; i++) {
        int row = wm0 + 16 * i + (lane & 15);
        a_r[i] = row * 64;
        a_z[i] = (row & 6) << 3;
    }
    const uint32_t gA = (lane >> 4) * 16;
    uint32_t b_r[2], b_z[2];
#pragma unroll
    for (int j = 0; j < 2; j++) {
        int row = wn0 + 16 * j + (lane & 7) + ((lane >> 4) << 3);
        b_r[j] = row * 64;
        b_z[j] = (row & 6) << 3;
    }
    const uint32_t gB = ((lane >> 3) & 1) * 16;

    float acc[4][4][4];
#pragma unroll
    for (int i = 0; i < 4; i++)
#pragma unroll
        for (int j = 0; j < 4; j++)
#pragma unroll
            for (int q = 0; q < 4; q++) acc[i][j][q] = 0.f;

    // prefetch issue: 8 x 16B per thread (2 per tile)
#define G_ISSUE(cc, ss)                                                        \
    do {                                                                       \
        const int k0_ = (cc) * 32;                                             \
        const uint32_t stb_ = sb + (ss) * 32768;                               \
        _Pragma("unroll")                                                      \
        for (int i_ = 0; i_ < 8; i_++) {                                       \
            const __nv_bfloat16* base_ =                                       \
                (i_ >> 1) == 0 ? bA0 : (i_ >> 1) == 1 ? bA1                    \
              : (i_ >> 1) == 2 ? bB0 : bB1;                                    \
            int w_ = tid + (i_ & 1) * 256;                                     \
            int r_ = w_ >> 2, c4_ = w_ & 3;                                    \
            cpa16(stb_ + (i_ >> 1) * 8192 + SWZ64(r_ * 64 + c4_ * 16),         \
                  base_ + (size_t)r_ * K + k0_ + c4_ * 8);                     \
        }                                                                      \
        CP_COMMIT();                                                           \
    } while (0)

    const int nch = K / 32;
    G_ISSUE(0, 0);
    G_ISSUE(1, 1);
    int s = 0;
    for (int c = 0; c < nch; c++) {
        // wait for stage c's group; keep later groups in flight
        if (c + 1 < nch) CP_WAIT1(); else CP_WAIT0();
        __syncthreads();                       // all warps done reading stage (c-1)%3
        if (c + 2 < nch) G_ISSUE(c + 2, (s + 2) % 3);

        const uint32_t stb = sb + s * 32768;
#pragma unroll
        for (int ks = 0; ks < 2; ks++) {
            const uint32_t off = ks * 32;
            uint32_t af[4][4], bh2[2][4], bl2[2][4];
#pragma unroll
            for (int i = 0; i < 4; i++)
                ldsm4(af[i], stb + a_r[i] + ((off + gA) ^ a_z[i]));
#pragma unroll
            for (int j = 0; j < 2; j++) {
                ldsm4(bh2[j], stb + 16384 + b_r[j] + ((off + gB) ^ b_z[j]));
                ldsm4(bl2[j], stb + 24576 + b_r[j] + ((off + gB) ^ b_z[j]));
            }
#pragma unroll
            for (int i = 0; i < 4; i++)
#pragma unroll
                for (int j = 0; j < 2; j++) {
                    mma16816(acc[i][j * 2 + 0], af[i], &bh2[j][0]);
                    mma16816(acc[i][j * 2 + 1], af[i], &bh2[j][2]);
                }
#pragma unroll
            for (int i = 0; i < 4; i++)
#pragma unroll
                for (int j = 0; j < 2; j++) {
                    mma16816(acc[i][j * 2 + 0], af[i], &bl2[j][0]);
                    mma16816(acc[i][j * 2 + 1], af[i], &bl2[j][2]);
                }
#pragma unroll
            for (int i = 0; i < 4; i++)
                ldsm4(af[i], stb + 8192 + a_r[i] + ((off + gA) ^ a_z[i]));
#pragma unroll
            for (int i = 0; i < 4; i++)
#pragma unroll
                for (int j = 0; j < 2; j++) {
                    mma16816(acc[i][j * 2 + 0], af[i], &bh2[j][0]);
                    mma16816(acc[i][j * 2 + 1], af[i], &bh2[j][2]);
                }
        }
        s = (s + 1) % 3;
    }
#undef G_ISSUE

    const int er = lane >> 2, ec = (lane & 3) * 2;
#pragma unroll
    for (int i = 0; i < 4; i++) {
        int r = m0 + wm0 + 16 * i + er;
#pragma unroll
        for (int j = 0; j < 4; j++) {
            int col = n0 + wn0 + 8 * j + ec;
            *(float2*)(C + (size_t)r * N + col)       = make_float2(acc[i][j][0], acc[i][j][1]);
            *(float2*)(C + (size_t)(r + 8) * N + col) = make_float2(acc[i][j][2], acc[i][j][3]);
        }
    }
}

// ---------------------------------------------------------------------------
// RoPE + head split; emit bf16 hi/lo Q(*0.125)/K/V in [BH][T][64]
// ---------------------------------------------------------------------------
__global__ void rope_split(const float* __restrict__ qkv)
{
    int idx = blockIdx.x * blockDim.x + threadIdx.x;
    int d  = idx & (ND - 1);
    int t  = (idx >> 6) & (NT - 1);
    int bh = idx >> 17;
    int b = bh >> 4, h = bh & (NH - 1);
    const float* base = qkv + (size_t)(b * NT + t) * (3 * NC);
    int col  = h * ND + d;
    int colm = h * ND + ((d + ND - 1) & (ND - 1));
    float qd = base[col],      qm = base[colm];
    float kd = base[NC + col], km = base[NC + colm];
    float vd = base[2 * NC + col];

    int fi = d & 31;
    float inv = expf(-(float)fi * (9.210340371976184f / 32.0f));
    float ang = (float)t * inv;
    float sn, cs;
    sincosf(ang, &sn, &cs);

    float qv = (qd * cs + qm * sn) * 0.125f;
    float kv = kd * cs + km * sn;

    __nv_bfloat16 hh;
    hh = __float2bfloat16(qv);
    g_qh[idx] = hh; g_ql[idx] = __float2bfloat16(qv - __bfloat162float(hh));
    hh = __float2bfloat16(kv);
    g_kh[idx] = hh; g_kl[idx] = __float2bfloat16(kv - __bfloat162float(hh));
    hh = __float2bfloat16(vd);
    g_vh[idx] = hh; g_vl[idx] = __float2bfloat16(vd - __bfloat162float(hh));
}

// ---------------------------------------------------------------------------
// Flash attention on HMMA, cp.async double-buffered K/V tiles (round-9 layout).
// smem: Q hi/lo 32KB @ sb; KV stages 32KB each @ sb+32768 + s*32768.
// ---------------------------------------------------------------------------
__global__ __launch_bounds__(256, 2) void flash_mma(
    const __nv_bfloat16* __restrict__ Qh_, const __nv_bfloat16* __restrict__ Ql_,
    const __nv_bfloat16* __restrict__ Kh_, const __nv_bfloat16* __restrict__ Kl_,
    const __nv_bfloat16* __restrict__ Vh_, const __nv_bfloat16* __restrict__ Vl_,
    __nv_bfloat16* __restrict__ Yh_, __nv_bfloat16* __restrict__ Yl_)
{
    extern __shared__ char smem[];
    const uint32_t sb = smem_u32(smem);
    const uint32_t sQh = sb, sQl = sb + 16384;

    const int bh = blockIdx.y, qi = blockIdx.x, q0 = qi * 128;
    const int tid = threadIdx.x, wid = tid >> 5, lane = tid & 31;
    const int wm = wid * 16;
    const size_t gbase = (size_t)bh * NT * ND;

    const __nv_bfloat16* pKh = Kh_ + gbase;
    const __nv_bfloat16* pKl = Kl_ + gbase;
    const __nv_bfloat16* pVh = Vh_ + gbase;
    const __nv_bfloat16* pVl = Vl_ + gbase;

    // ---- load Q hi/lo (128x64, SW128) ----
    {
        const __nv_bfloat16* s0 = Qh_ + gbase + (size_t)q0 * ND;
        const __nv_bfloat16* s1 = Ql_ + gbase + (size_t)q0 * ND;
#pragma unroll
        for (int i = 0; i < 4; i++) {
            int idx = tid + i * 256;
            int r = idx >> 3, c8 = idx & 7;
            uint32_t off = SWZ(r * 128 + c8 * 16);
            uint4 v = *(const uint4*)(s0 + (size_t)r * ND + c8 * 8);
            asm volatile("st.shared.v4.b32 [%0], {%1,%2,%3,%4};"
                         :: "r"(sQh + off), "r"(v.x), "r"(v.y), "r"(v.z), "r"(v.w));
            uint4 w = *(const uint4*)(s1 + (size_t)r * ND + c8 * 8);
            asm volatile("st.shared.v4.b32 [%0], {%1,%2,%3,%4};"
                         :: "r"(sQl + off), "r"(w.x), "r"(w.y), "r"(w.z), "r"(w.w));
        }
    }

    // KV prefetch: tiles Kh@0 Kl@8192 Vh@16384 Vl@24576 within stage
#define F_ISSUE(kt_, ss)                                                       \
    do {                                                                       \
        const size_t ko_ = (size_t)(kt_) * 64 * ND;                            \
        const uint32_t kvb_ = sb + 32768 + (ss) * 32768;                       \
        _Pragma("unroll")                                                      \
        for (int i_ = 0; i_ < 8; i_++) {                                       \
            const __nv_bfloat16* base_ =                                       \
                (i_ >> 1) == 0 ? pKh : (i_ >> 1) == 1 ? pKl                    \
              : (i_ >> 1) == 2 ? pVh : pVl;                                    \
            int w_ = tid + (i_ & 1) * 256;                                     \
            int r_ = w_ >> 3, c8_ = w_ & 7;                                    \
            cpa16(kvb_ + (i_ >> 1) * 8192 + SWZ(r_ * 128 + c8_ * 16),          \
                  base_ + ko_ + (size_t)r_ * ND + c8_ * 8);                    \
        }                                                                      \
        CP_COMMIT();                                                           \
    } while (0)

    // per-lane fragment address components
    const int rowA = wm + (lane & 15);
    const uint32_t aoff = rowA * 128, aswz = (rowA & 7) * 16;
    const uint32_t gA = (lane >> 4) * 16;
    const int rowB_ = (lane & 7) + ((lane >> 4) << 3);        // K (non-trans)
    const uint32_t bswz = (rowB_ & 7) * 16;
    const uint32_t gB = ((lane >> 3) & 1) * 16;
    const int rowV_ = ((lane >> 3) & 1) * 8 + (lane & 7);     // V (trans)
    const uint32_t vswz = (lane & 7) * 16;
    const uint32_t gV = (lane >> 4) * 16;

    float m0 = -1e30f, m1 = -1e30f, l0 = 0.f, l1 = 0.f;
    float oacc[8][4];
#pragma unroll
    for (int j = 0; j < 8; j++)
#pragma unroll
        for (int e = 0; e < 4; e++) oacc[j][e] = 0.f;

    const int nkt = 2 * qi + 2;
    F_ISSUE(0, 0);
    for (int kt = 0; kt < nkt; kt++) {
        const int s = kt & 1;
        if (kt + 1 < nkt) { F_ISSUE(kt + 1, s ^ 1); CP_WAIT1(); }
        else              { CP_WAIT0(); }
        __syncthreads();

        const uint32_t kvb = sb + 32768 + s * 32768;
        const uint32_t sKh = kvb, sKl = kvb + 8192;
        const uint32_t sVh = kvb + 16384, sVl = kvb + 24576;

        if (kt * 64 <= q0 + wm + 15) {   // not fully masked for this warp
            // ---- S = Q K^T (bf16x3) ----
            float sacc[8][4];
#pragma unroll
            for (int j = 0; j < 8; j++)
#pragma unroll
                for (int e = 0; e < 4; e++) sacc[j][e] = 0.f;

#pragma unroll
            for (int ks = 0; ks < 4; ks++) {
                const uint32_t ks32 = ks * 32;
                uint32_t aqh[4], aql[4];
                ldsm4(aqh, sQh + aoff + ((ks32 + gA) ^ aswz));
                ldsm4(aql, sQl + aoff + ((ks32 + gA) ^ aswz));
#pragma unroll
                for (int jb = 0; jb < 4; jb++) {
                    uint32_t roff = (jb * 16 + rowB_) * 128 + ((ks32 + gB) ^ bswz);
                    uint32_t kh4[4], kl4[4];
                    ldsm4(kh4, sKh + roff);
                    ldsm4(kl4, sKl + roff);
                    mma16816(sacc[2 * jb + 0], aqh, &kh4[0]);
                    mma16816(sacc[2 * jb + 1], aqh, &kh4[2]);
                    mma16816(sacc[2 * jb + 0], aqh, &kl4[0]);
                    mma16816(sacc[2 * jb + 1], aqh, &kl4[2]);
                    mma16816(sacc[2 * jb + 0], aql, &kh4[0]);
                    mma16816(sacc[2 * jb + 1], aql, &kh4[2]);
                }
            }

            // ---- causal mask ----
            if ((kt + 1) * 64 - 1 > q0 + wm) {
                const int rb = q0 + wm + (lane >> 2);
                const int cb = kt * 64 + (lane & 3) * 2;
#pragma unroll
                for (int t = 0; t < 8; t++) {
                    int c = cb + t * 8;
                    if (c     > rb)     sacc[t][0] = -1e30f;
                    if (c + 1 > rb)     sacc[t][1] = -1e30f;
                    if (c     > rb + 8) sacc[t][2] = -1e30f;
                    if (c + 1 > rb + 8) sacc[t][3] = -1e30f;
                }
            }

            // ---- online softmax ----
            {
                float mx0 = -1e30f, mx1 = -1e30f;
#pragma unroll
                for (int t = 0; t < 8; t++) {
                    mx0 = fmaxf(mx0, fmaxf(sacc[t][0], sacc[t][1]));
                    mx1 = fmaxf(mx1, fmaxf(sacc[t][2], sacc[t][3]));
                }
                mx0 = fmaxf(mx0, __shfl_xor_sync(0xffffffffu, mx0, 1));
                mx0 = fmaxf(mx0, __shfl_xor_sync(0xffffffffu, mx0, 2));
                mx1 = fmaxf(mx1, __shfl_xor_sync(0xffffffffu, mx1, 1));
                mx1 = fmaxf(mx1, __shfl_xor_sync(0xffffffffu, mx1, 2));
                float mn0 = fmaxf(m0, mx0), mn1 = fmaxf(m1, mx1);
                float a0 = __expf(m0 - mn0), a1 = __expf(m1 - mn1);
                m0 = mn0; m1 = mn1;
                float ls0 = 0.f, ls1 = 0.f;
#pragma unroll
                for (int t = 0; t < 8; t++) {
                    sacc[t][0] = __expf(sacc[t][0] - mn0);
                    sacc[t][1] = __expf(sacc[t][1] - mn0);
                    sacc[t][2] = __expf(sacc[t][2] - mn1);
                    sacc[t][3] = __expf(sacc[t][3] - mn1);
                    ls0 += sacc[t][0] + sacc[t][1];
                    ls1 += sacc[t][2] + sacc[t][3];
                }
                ls0 += __shfl_xor_sync(0xffffffffu, ls0, 1);
                ls0 += __shfl_xor_sync(0xffffffffu, ls0, 2);
                ls1 += __shfl_xor_sync(0xffffffffu, ls1, 1);
                ls1 += __shfl_xor_sync(0xffffffffu, ls1, 2);
                l0 = l0 * a0 + ls0;
                l1 = l1 * a1 + ls1;
#pragma unroll
                for (int j = 0; j < 8; j++) {
                    oacc[j][0] *= a0; oacc[j][1] *= a0;
                    oacc[j][2] *= a1; oacc[j][3] *= a1;
                }
            }

            // ---- O += P V (bf16x3, P from registers) ----
#pragma unroll
            for (int ks = 0; ks < 4; ks++) {
                uint32_t ah[4], al[4];
                ah[0] = packf(sacc[2*ks][0],   sacc[2*ks][1]);
                ah[1] = packf(sacc[2*ks][2],   sacc[2*ks][3]);
                ah[2] = packf(sacc[2*ks+1][0], sacc[2*ks+1][1]);
                ah[3] = packf(sacc[2*ks+1][2], sacc[2*ks+1][3]);
#pragma unroll
                for (int r = 0; r < 4; r++) {
                    float flo = __uint_as_float(ah[r] << 16);
                    float fhi = __uint_as_float(ah[r] & 0xffff0000u);
                    float s0 = sacc[2*ks + (r >> 1)][(r & 1) * 2 + 0];
                    float s1 = sacc[2*ks + (r >> 1)][(r & 1) * 2 + 1];
                    al[r] = packf(s0 - flo, s1 - fhi);
                }
                const uint32_t vrow = (ks * 16 + rowV_) * 128;
#pragma unroll
                for (int jb = 0; jb < 4; jb++) {
                    uint32_t voff = vrow + ((jb * 32 + gV) ^ vswz);
                    uint32_t vh4[4], vl4[4];
                    ldsm4t(vh4, sVh + voff);
                    ldsm4t(vl4, sVl + voff);
                    mma16816(oacc[2 * jb + 0], ah, &vh4[0]);
                    mma16816(oacc[2 * jb + 1], ah, &vh4[2]);
                    mma16816(oacc[2 * jb + 0], ah, &vl4[0]);
                    mma16816(oacc[2 * jb + 1], ah, &vl4[2]);
                    mma16816(oacc[2 * jb + 0], al, &vh4[0]);
                    mma16816(oacc[2 * jb + 1], al, &vh4[2]);
                }
            }
        }
        __syncthreads();   // stage reusable for prefetch next iteration
    }
#undef F_ISSUE

    // ---- epilogue ----
    {
        const int b = bh >> 4, h = bh & (NH - 1);
        const float i0 = 1.f / l0, i1 = 1.f / l1;
        const int t0 = q0 + wm + (lane >> 2);
        const int c0 = h * ND + (lane & 3) * 2;
#pragma unroll
        for (int j = 0; j < 8; j++) {
            float v0 = oacc[j][0] * i0, v1 = oacc[j][1] * i0;
            float v2 = oacc[j][2] * i1, v3 = oacc[j][3] * i1;
            uint32_t ph0 = packf(v0, v1), ph1 = packf(v2, v3);
            uint32_t pl0 = packf(v0 - __uint_as_float(ph0 << 16),
                                 v1 - __uint_as_float(ph0 & 0xffff0000u));
            uint32_t pl1 = packf(v2 - __uint_as_float(ph1 << 16),
                                 v3 - __uint_as_float(ph1 & 0xffff0000u));
            size_t o0 = (size_t)(b * NT + t0) * NC + c0 + j * 8;
            size_t o1 = (size_t)(b * NT + t0 + 8) * NC + c0 + j * 8;
            *(uint32_t*)(Yh_ + o0) = ph0;
            *(uint32_t*)(Yl_ + o0) = pl0;
            *(uint32_t*)(Yh_ + o1) = ph1;
            *(uint32_t*)(Yl_ + o1) = pl1;
        }
    }
}

// ---------------------------------------------------------------------------
extern "C" void kernel_launch(void* const* d_in, const int* in_sizes, int n_in,
                              void* d_out, int out_size)
{
    const float* x  = (const float*)d_in[0];
    const float* Wa = (const float*)d_in[1];
    const float* Wp = (const float*)d_in[2];
    float* out = (float*)d_out;

    float* qkv;
    __nv_bfloat16 *xh, *xl, *yh, *yl, *wah, *wal, *wph, *wpl;
    __nv_bfloat16 *qh, *ql, *kh, *kl, *vh, *vl;
    cudaGetSymbolAddress((void**)&qkv, g_qkv);
    cudaGetSymbolAddress((void**)&xh,  g_xh);
    cudaGetSymbolAddress((void**)&xl,  g_xl);
    cudaGetSymbolAddress((void**)&yh,  g_yh);
    cudaGetSymbolAddress((void**)&yl,  g_yl);
    cudaGetSymbolAddress((void**)&wah, g_wah);
    cudaGetSymbolAddress((void**)&wal, g_wal);
    cudaGetSymbolAddress((void**)&wph, g_wph);
    cudaGetSymbolAddress((void**)&wpl, g_wpl);
    cudaGetSymbolAddress((void**)&qh,  g_qh);
    cudaGetSymbolAddress((void**)&ql,  g_ql);
    cudaGetSymbolAddress((void**)&kh,  g_kh);
    cudaGetSymbolAddress((void**)&kl,  g_kl);
    cudaGetSymbolAddress((void**)&vh,  g_vh);
    cudaGetSymbolAddress((void**)&vl,  g_vl);

    const int gemm_smem = 98304;          // 3 stages x 32KB
    cudaFuncSetAttribute(gemm_mma, cudaFuncAttributeMaxDynamicSharedMemorySize, gemm_smem);
    const int flash_smem = 98304;         // Q 32KB + 2 stages x 32KB
    cudaFuncSetAttribute(flash_mma, cudaFuncAttributeMaxDynamicSharedMemorySize, flash_smem);

    // 0) input splits / weight transposes
    cvt_split<<<(NM * NC) / 1024, 256>>>(x, xh, xl);
    wt_split<<<dim3(3 * NC / 32, NC / 32), dim3(32, 8)>>>(Wa, wah, wal, NC, 3 * NC);
    wt_split<<<dim3(NC / 32, NC / 32), dim3(32, 8)>>>(Wp, wph, wpl, NC, NC);

    // 1) QKV = x @ W_attn
    gemm_mma<<<dim3(3 * NC / 128, NM / 128), 256, gemm_smem>>>(
        xh, xl, wah, wal, qkv, NM, 3 * NC, NC);

    // 2) RoPE + split to bf16 hi/lo heads
    rope_split<<<(NBH * NT * ND) / 256, 256>>>(qkv);

    // 3) Flash attention (causal) on tensor cores -> yh/yl
    flash_mma<<<dim3(NT / 128, NBH), 256, flash_smem>>>(
        qh, ql, kh, kl, vh, vl, yh, yl);

    // 4) out = y @ W_proj
    gemm_mma<<<dim3(NC / 128, NM / 128), 256, gemm_smem>>>(
        yh, yl, wph, wpl, out, NM, NC, NC);
}

// round 11
// speedup vs baseline: 6.6052x; 1.0440x over previous
#include <cuda_runtime.h>
#include <cuda_bf16.h>
#include <math.h>
#include <stdint.h>

#define NB 2
#define NT 2048
#define NC 1024
#define NH 16
#define ND 64
#define NBH (NB*NH)
#define NM (NB*NT)   // 4096 rows

// ---------------------------------------------------------------------------
// Scratch (static device allocations)
// ---------------------------------------------------------------------------
__device__ float g_qkv[(size_t)NM * 3 * NC];            // [4096, 3072]

__device__ __nv_bfloat16 g_xh[(size_t)NM * NC];         // x hi/lo
__device__ __nv_bfloat16 g_xl[(size_t)NM * NC];
__device__ __nv_bfloat16 g_yh[(size_t)NM * NC];         // attn out hi/lo
__device__ __nv_bfloat16 g_yl[(size_t)NM * NC];
__device__ __nv_bfloat16 g_wah[(size_t)(3*NC) * NC];    // Wa^T hi/lo [3072][1024]
__device__ __nv_bfloat16 g_wal[(size_t)(3*NC) * NC];
__device__ __nv_bfloat16 g_wph[(size_t)NC * NC];        // Wp^T hi/lo
__device__ __nv_bfloat16 g_wpl[(size_t)NC * NC];

__device__ __nv_bfloat16 g_qh[(size_t)NBH * NT * ND];   // RoPE'd Q*scale hi/lo
__device__ __nv_bfloat16 g_ql[(size_t)NBH * NT * ND];
__device__ __nv_bfloat16 g_kh[(size_t)NBH * NT * ND];
__device__ __nv_bfloat16 g_kl[(size_t)NBH * NT * ND];
__device__ __nv_bfloat16 g_vh[(size_t)NBH * NT * ND];
__device__ __nv_bfloat16 g_vl[(size_t)NBH * NT * ND];

// ---------------------------------------------------------------------------
__device__ __forceinline__ uint32_t smem_u32(const void* p) {
    uint32_t a;
    asm("{ .reg .u64 t; cvta.to.shared.u64 t, %1; cvt.u32.u64 %0, t; }"
        : "=r"(a) : "l"(p));
    return a;
}
#define SWZ(o)   ((o) ^ (((o) >> 3) & 0x70))   // SW128 (128B rows)
#define SWZ64(o) ((o) ^ (((o) >> 3) & 0x30))   // SW64  (64B rows)

__device__ __forceinline__ void cpa16(uint32_t dst, const void* src) {
    asm volatile("cp.async.cg.shared.global [%0], [%1], 16;"
                 :: "r"(dst), "l"(src) : "memory");
}
#define CP_COMMIT() asm volatile("cp.async.commit_group;" ::: "memory")
#define CP_WAIT1()  asm volatile("cp.async.wait_group 1;" ::: "memory")
#define CP_WAIT0()  asm volatile("cp.async.wait_group 0;" ::: "memory")

__device__ __forceinline__ void ldsm4(uint32_t* r, uint32_t addr) {
    asm volatile("ldmatrix.sync.aligned.m8n8.x4.shared.b16 {%0,%1,%2,%3}, [%4];"
                 : "=r"(r[0]), "=r"(r[1]), "=r"(r[2]), "=r"(r[3]) : "r"(addr));
}
__device__ __forceinline__ void ldsm4t(uint32_t* r, uint32_t addr) {
    asm volatile("ldmatrix.sync.aligned.m8n8.x4.trans.shared.b16 {%0,%1,%2,%3}, [%4];"
                 : "=r"(r[0]), "=r"(r[1]), "=r"(r[2]), "=r"(r[3]) : "r"(addr));
}
__device__ __forceinline__ void mma16816(float* d, const uint32_t* a, const uint32_t* b) {
    asm volatile(
        "mma.sync.aligned.m16n8k16.row.col.f32.bf16.bf16.f32 "
        "{%0,%1,%2,%3}, {%4,%5,%6,%7}, {%8,%9}, {%0,%1,%2,%3};"
        : "+f"(d[0]), "+f"(d[1]), "+f"(d[2]), "+f"(d[3])
        : "r"(a[0]), "r"(a[1]), "r"(a[2]), "r"(a[3]), "r"(b[0]), "r"(b[1]));
}
__device__ __forceinline__ uint32_t packf(float lo, float hi) {
    uint32_t d;
    asm("cvt.rn.bf16x2.f32 %0, %1, %2;" : "=r"(d) : "f"(hi), "f"(lo));
    return d;
}

// ---------------------------------------------------------------------------
// Elementwise fp32 -> bf16 hi/lo split
// ---------------------------------------------------------------------------
__global__ void cvt_split(const float* __restrict__ in,
                          __nv_bfloat16* __restrict__ h,
                          __nv_bfloat16* __restrict__ l) {
    int i = (blockIdx.x * blockDim.x + threadIdx.x) * 4;
    float4 a = *(const float4*)(in + i);
    float v[4] = {a.x, a.y, a.z, a.w};
    __nv_bfloat16 hh[4], ll[4];
#pragma unroll
    for (int j = 0; j < 4; j++) {
        hh[j] = __float2bfloat16(v[j]);
        ll[j] = __float2bfloat16(v[j] - __bfloat162float(hh[j]));
    }
    *(__nv_bfloat162*)(h + i)     = *(__nv_bfloat162*)&hh[0];
    *(__nv_bfloat162*)(h + i + 2) = *(__nv_bfloat162*)&hh[2];
    *(__nv_bfloat162*)(l + i)     = *(__nv_bfloat162*)&ll[0];
    *(__nv_bfloat162*)(l + i + 2) = *(__nv_bfloat162*)&ll[2];
}

// ---------------------------------------------------------------------------
// W [K][N] fp32 -> W^T hi/lo [N][K] bf16
// ---------------------------------------------------------------------------
__global__ void wt_split(const float* __restrict__ W,
                         __nv_bfloat16* __restrict__ Th,
                         __nv_bfloat16* __restrict__ Tl, int K, int N) {
    __shared__ float t[32][33];
    int n0 = blockIdx.x * 32, k0 = blockIdx.y * 32;
    int tx = threadIdx.x, ty0 = threadIdx.y;
#pragma unroll
    for (int i = 0; i < 4; i++) {
        int ty = ty0 + i * 8;
        t[ty][tx] = W[(size_t)(k0 + ty) * N + n0 + tx];
    }
    __syncthreads();
#pragma unroll
    for (int i = 0; i < 4; i++) {
        int ty = ty0 + i * 8;
        float a = t[tx][ty];
        __nv_bfloat16 h = __float2bfloat16(a);
        __nv_bfloat16 l = __float2bfloat16(a - __bfloat162float(h));
        Th[(size_t)(n0 + ty) * K + k0 + tx] = h;
        Tl[(size_t)(n0 + ty) * K + k0 + tx] = l;
    }
}

// ---------------------------------------------------------------------------
// HMMA bf16x3 GEMM: CTA 128x128, 4 warps (warp tile 64x64), 3-stage cp.async.
// Per k16 step/warp: 16 ldsm4 -> 96 MMA (6:1). K-chunk 32, SW64 smem.
// ---------------------------------------------------------------------------
__global__ __launch_bounds__(128, 2) void gemm_mma(
    const __nv_bfloat16* __restrict__ Ah, const __nv_bfloat16* __restrict__ Al,
    const __nv_bfloat16* __restrict__ Bh, const __nv_bfloat16* __restrict__ Bl,
    float* __restrict__ C, int M, int N, int K) {
    extern __shared__ char smem[];
    const uint32_t sb = smem_u32(smem);   // stage s at sb + s*32768
                                          // tiles: Ah@0 Al@8192 Bh@16384 Bl@24576
    const int tid = threadIdx.x, wid = tid >> 5, lane = tid & 31;
    const int m0 = blockIdx.y * 128, n0 = blockIdx.x * 128;
    const int wm0 = (wid >> 1) * 64, wn0 = (wid & 1) * 64;

    const __nv_bfloat16* bA0 = Ah + (size_t)m0 * K;
    const __nv_bfloat16* bA1 = Al + (size_t)m0 * K;
    const __nv_bfloat16* bB0 = Bh + (size_t)n0 * K;
    const __nv_bfloat16* bB1 = Bl + (size_t)n0 * K;

    // fragment addresses (64B rows, SW64)
    uint32_t a_r[4], a_z[4];
#pragma unroll
    for (int i = 0; i < 4; i++) {
        int row = wm0 + 16 * i + (lane & 15);
        a_r[i] = row * 64;
        a_z[i] = (row & 6) << 3;
    }
    const uint32_t gA = (lane >> 4) * 16;
    uint32_t b_r[4], b_z[4];
#pragma unroll
    for (int j = 0; j < 4; j++) {
        int row = wn0 + 16 * j + (lane & 7) + ((lane >> 4) << 3);
        b_r[j] = row * 64;
        b_z[j] = (row & 6) << 3;
    }
    const uint32_t gB = ((lane >> 3) & 1) * 16;

    float acc[4][8][4];
#pragma unroll
    for (int i = 0; i < 4; i++)
#pragma unroll
        for (int j = 0; j < 8; j++)
#pragma unroll
            for (int q = 0; q < 4; q++) acc[i][j][q] = 0.f;

    // prefetch issue: 16 x 16B per thread (4 per tile), 128 threads
#define G_ISSUE(cc, ss)                                                        \
    do {                                                                       \
        const int k0_ = (cc) * 32;                                             \
        const uint32_t stb_ = sb + (ss) * 32768;                               \
        _Pragma("unroll")                                                      \
        for (int i_ = 0; i_ < 16; i_++) {                                      \
            const __nv_bfloat16* base_ =                                       \
                (i_ >> 2) == 0 ? bA0 : (i_ >> 2) == 1 ? bA1                    \
              : (i_ >> 2) == 2 ? bB0 : bB1;                                    \
            int w_ = tid + (i_ & 3) * 128;                                     \
            int r_ = w_ >> 2, c4_ = w_ & 3;                                    \
            cpa16(stb_ + (i_ >> 2) * 8192 + SWZ64(r_ * 64 + c4_ * 16),         \
                  base_ + (size_t)r_ * K + k0_ + c4_ * 8);                     \
        }                                                                      \
        CP_COMMIT();                                                           \
    } while (0)

    const int nch = K / 32;
    G_ISSUE(0, 0);
    G_ISSUE(1, 1);
    int s = 0;
    for (int c = 0; c < nch; c++) {
        if (c + 1 < nch) CP_WAIT1(); else CP_WAIT0();
        __syncthreads();                       // all warps done reading stage (c-1)%3
        if (c + 2 < nch) G_ISSUE(c + 2, (s + 2) % 3);

        const uint32_t stb = sb + s * 32768;
#pragma unroll
        for (int ks = 0; ks < 2; ks++) {
            const uint32_t off = ks * 32;
            uint32_t af[4][4], bh2[4][4], bl2[4][4];
            // A-hi + B-hi + B-lo fragments
#pragma unroll
            for (int i = 0; i < 4; i++)
                ldsm4(af[i], stb + a_r[i] + ((off + gA) ^ a_z[i]));
#pragma unroll
            for (int j = 0; j < 4; j++) {
                ldsm4(bh2[j], stb + 16384 + b_r[j] + ((off + gB) ^ b_z[j]));
                ldsm4(bl2[j], stb + 24576 + b_r[j] + ((off + gB) ^ b_z[j]));
            }
            // pass 1: Ah * Bh
#pragma unroll
            for (int i = 0; i < 4; i++)
#pragma unroll
                for (int j = 0; j < 4; j++) {
                    mma16816(acc[i][j * 2 + 0], af[i], &bh2[j][0]);
                    mma16816(acc[i][j * 2 + 1], af[i], &bh2[j][2]);
                }
            // pass 2: Ah * Bl
#pragma unroll
            for (int i = 0; i < 4; i++)
#pragma unroll
                for (int j = 0; j < 4; j++) {
                    mma16816(acc[i][j * 2 + 0], af[i], &bl2[j][0]);
                    mma16816(acc[i][j * 2 + 1], af[i], &bl2[j][2]);
                }
            // pass 3: Al * Bh (reuse af regs)
#pragma unroll
            for (int i = 0; i < 4; i++)
                ldsm4(af[i], stb + 8192 + a_r[i] + ((off + gA) ^ a_z[i]));
#pragma unroll
            for (int i = 0; i < 4; i++)
#pragma unroll
                for (int j = 0; j < 4; j++) {
                    mma16816(acc[i][j * 2 + 0], af[i], &bh2[j][0]);
                    mma16816(acc[i][j * 2 + 1], af[i], &bh2[j][2]);
                }
        }
        s = (s + 1) % 3;
    }
#undef G_ISSUE

    const int er = lane >> 2, ec = (lane & 3) * 2;
#pragma unroll
    for (int i = 0; i < 4; i++) {
        int r = m0 + wm0 + 16 * i + er;
#pragma unroll
        for (int j = 0; j < 8; j++) {
            int col = n0 + wn0 + 8 * j + ec;
            *(float2*)(C + (size_t)r * N + col)       = make_float2(acc[i][j][0], acc[i][j][1]);
            *(float2*)(C + (size_t)(r + 8) * N + col) = make_float2(acc[i][j][2], acc[i][j][3]);
        }
    }
}

// ---------------------------------------------------------------------------
// RoPE + head split; emit bf16 hi/lo Q(*0.125)/K/V in [BH][T][64]
// ---------------------------------------------------------------------------
__global__ void rope_split(const float* __restrict__ qkv)
{
    int idx = blockIdx.x * blockDim.x + threadIdx.x;
    int d  = idx & (ND - 1);
    int t  = (idx >> 6) & (NT - 1);
    int bh = idx >> 17;
    int b = bh >> 4, h = bh & (NH - 1);
    const float* base = qkv + (size_t)(b * NT + t) * (3 * NC);
    int col  = h * ND + d;
    int colm = h * ND + ((d + ND - 1) & (ND - 1));
    float qd = base[col],      qm = base[colm];
    float kd = base[NC + col], km = base[NC + colm];
    float vd = base[2 * NC + col];

    int fi = d & 31;
    float inv = expf(-(float)fi * (9.210340371976184f / 32.0f));
    float ang = (float)t * inv;
    float sn, cs;
    sincosf(ang, &sn, &cs);

    float qv = (qd * cs + qm * sn) * 0.125f;
    float kv = kd * cs + km * sn;

    __nv_bfloat16 hh;
    hh = __float2bfloat16(qv);
    g_qh[idx] = hh; g_ql[idx] = __float2bfloat16(qv - __bfloat162float(hh));
    hh = __float2bfloat16(kv);
    g_kh[idx] = hh; g_kl[idx] = __float2bfloat16(kv - __bfloat162float(hh));
    hh = __float2bfloat16(vd);
    g_vh[idx] = hh; g_vl[idx] = __float2bfloat16(vd - __bfloat162float(hh));
}

// ---------------------------------------------------------------------------
// Flash attention on HMMA, cp.async double-buffered K/V tiles.
// smem: Q hi/lo 32KB @ sb; KV stages 32KB each @ sb+32768 + s*32768.
// ---------------------------------------------------------------------------
__global__ __launch_bounds__(256, 2) void flash_mma(
    const __nv_bfloat16* __restrict__ Qh_, const __nv_bfloat16* __restrict__ Ql_,
    const __nv_bfloat16* __restrict__ Kh_, const __nv_bfloat16* __restrict__ Kl_,
    const __nv_bfloat16* __restrict__ Vh_, const __nv_bfloat16* __restrict__ Vl_,
    __nv_bfloat16* __restrict__ Yh_, __nv_bfloat16* __restrict__ Yl_)
{
    extern __shared__ char smem[];
    const uint32_t sb = smem_u32(smem);
    const uint32_t sQh = sb, sQl = sb + 16384;

    const int bh = blockIdx.y, qi = blockIdx.x, q0 = qi * 128;
    const int tid = threadIdx.x, wid = tid >> 5, lane = tid & 31;
    const int wm = wid * 16;
    const size_t gbase = (size_t)bh * NT * ND;

    const __nv_bfloat16* pKh = Kh_ + gbase;
    const __nv_bfloat16* pKl = Kl_ + gbase;
    const __nv_bfloat16* pVh = Vh_ + gbase;
    const __nv_bfloat16* pVl = Vl_ + gbase;

    // ---- load Q hi/lo (128x64, SW128) ----
    {
        const __nv_bfloat16* s0 = Qh_ + gbase + (size_t)q0 * ND;
        const __nv_bfloat16* s1 = Ql_ + gbase + (size_t)q0 * ND;
#pragma unroll
        for (int i = 0; i < 4; i++) {
            int idx = tid + i * 256;
            int r = idx >> 3, c8 = idx & 7;
            uint32_t off = SWZ(r * 128 + c8 * 16);
            uint4 v = *(const uint4*)(s0 + (size_t)r * ND + c8 * 8);
            asm volatile("st.shared.v4.b32 [%0], {%1,%2,%3,%4};"
                         :: "r"(sQh + off), "r"(v.x), "r"(v.y), "r"(v.z), "r"(v.w));
            uint4 w = *(const uint4*)(s1 + (size_t)r * ND + c8 * 8);
            asm volatile("st.shared.v4.b32 [%0], {%1,%2,%3,%4};"
                         :: "r"(sQl + off), "r"(w.x), "r"(w.y), "r"(w.z), "r"(w.w));
        }
    }

    // KV prefetch: tiles Kh@0 Kl@8192 Vh@16384 Vl@24576 within stage
#define F_ISSUE(kt_, ss)                                                       \
    do {                                                                       \
        const size_t ko_ = (size_t)(kt_) * 64 * ND;                            \
        const uint32_t kvb_ = sb + 32768 + (ss) * 32768;                       \
        _Pragma("unroll")                                                      \
        for (int i_ = 0; i_ < 8; i_++) {                                       \
            const __nv_bfloat16* base_ =                                       \
                (i_ >> 1) == 0 ? pKh : (i_ >> 1) == 1 ? pKl                    \
              : (i_ >> 1) == 2 ? pVh : pVl;                                    \
            int w_ = tid + (i_ & 1) * 256;                                     \
            int r_ = w_ >> 3, c8_ = w_ & 7;                                    \
            cpa16(kvb_ + (i_ >> 1) * 8192 + SWZ(r_ * 128 + c8_ * 16),          \
                  base_ + ko_ + (size_t)r_ * ND + c8_ * 8);                    \
        }                                                                      \
        CP_COMMIT();                                                           \
    } while (0)

    // per-lane fragment address components
    const int rowA = wm + (lane & 15);
    const uint32_t aoff = rowA * 128, aswz = (rowA & 7) * 16;
    const uint32_t gA = (lane >> 4) * 16;
    const int rowB_ = (lane & 7) + ((lane >> 4) << 3);        // K (non-trans)
    const uint32_t bswz = (rowB_ & 7) * 16;
    const uint32_t gB = ((lane >> 3) & 1) * 16;
    const int rowV_ = ((lane >> 3) & 1) * 8 + (lane & 7);     // V (trans)
    const uint32_t vswz = (lane & 7) * 16;
    const uint32_t gV = (lane >> 4) * 16;

    float m0 = -1e30f, m1 = -1e30f, l0 = 0.f, l1 = 0.f;
    float oacc[8][4];
#pragma unroll
    for (int j = 0; j < 8; j++)
#pragma unroll
        for (int e = 0; e < 4; e++) oacc[j][e] = 0.f;

    const int nkt = 2 * qi + 2;
    F_ISSUE(0, 0);
    for (int kt = 0; kt < nkt; kt++) {
        const int s = kt & 1;
        if (kt + 1 < nkt) { F_ISSUE(kt + 1, s ^ 1); CP_WAIT1(); }
        else              { CP_WAIT0(); }
        __syncthreads();

        const uint32_t kvb = sb + 32768 + s * 32768;
        const uint32_t sKh = kvb, sKl = kvb + 8192;
        const uint32_t sVh = kvb + 16384, sVl = kvb + 24576;

        if (kt * 64 <= q0 + wm + 15) {   // not fully masked for this warp
            // ---- S = Q K^T (bf16x3) ----
            float sacc[8][4];
#pragma unroll
            for (int j = 0; j < 8; j++)
#pragma unroll
                for (int e = 0; e < 4; e++) sacc[j][e] = 0.f;

#pragma unroll
            for (int ks = 0; ks < 4; ks++) {
                const uint32_t ks32 = ks * 32;
                uint32_t aqh[4], aql[4];
                ldsm4(aqh, sQh + aoff + ((ks32 + gA) ^ aswz));
                ldsm4(aql, sQl + aoff + ((ks32 + gA) ^ aswz));
#pragma unroll
                for (int jb = 0; jb < 4; jb++) {
                    uint32_t roff = (jb * 16 + rowB_) * 128 + ((ks32 + gB) ^ bswz);
                    uint32_t kh4[4], kl4[4];
                    ldsm4(kh4, sKh + roff);
                    ldsm4(kl4, sKl + roff);
                    mma16816(sacc[2 * jb + 0], aqh, &kh4[0]);
                    mma16816(sacc[2 * jb + 1], aqh, &kh4[2]);
                    mma16816(sacc[2 * jb + 0], aqh, &kl4[0]);
                    mma16816(sacc[2 * jb + 1], aqh, &kl4[2]);
                    mma16816(sacc[2 * jb + 0], aql, &kh4[0]);
                    mma16816(sacc[2 * jb + 1], aql, &kh4[2]);
                }
            }

            // ---- causal mask ----
            if ((kt + 1) * 64 - 1 > q0 + wm) {
                const int rb = q0 + wm + (lane >> 2);
                const int cb = kt * 64 + (lane & 3) * 2;
#pragma unroll
                for (int t = 0; t < 8; t++) {
                    int c = cb + t * 8;
                    if (c     > rb)     sacc[t][0] = -1e30f;
                    if (c + 1 > rb)     sacc[t][1] = -1e30f;
                    if (c     > rb + 8) sacc[t][2] = -1e30f;
                    if (c + 1 > rb + 8) sacc[t][3] = -1e30f;
                }
            }

            // ---- online softmax ----
            {
                float mx0 = -1e30f, mx1 = -1e30f;
#pragma unroll
                for (int t = 0; t < 8; t++) {
                    mx0 = fmaxf(mx0, fmaxf(sacc[t][0], sacc[t][1]));
                    mx1 = fmaxf(mx1, fmaxf(sacc[t][2], sacc[t][3]));
                }
                mx0 = fmaxf(mx0, __shfl_xor_sync(0xffffffffu, mx0, 1));
                mx0 = fmaxf(mx0, __shfl_xor_sync(0xffffffffu, mx0, 2));
                mx1 = fmaxf(mx1, __shfl_xor_sync(0xffffffffu, mx1, 1));
                mx1 = fmaxf(mx1, __shfl_xor_sync(0xffffffffu, mx1, 2));
                float mn0 = fmaxf(m0, mx0), mn1 = fmaxf(m1, mx1);
                float a0 = __expf(m0 - mn0), a1 = __expf(m1 - mn1);
                m0 = mn0; m1 = mn1;
                float ls0 = 0.f, ls1 = 0.f;
#pragma unroll
                for (int t = 0; t < 8; t++) {
                    sacc[t][0] = __expf(sacc[t][0] - mn0);
                    sacc[t][1] = __expf(sacc[t][1] - mn0);
                    sacc[t][2] = __expf(sacc[t][2] - mn1);
                    sacc[t][3] = __expf(sacc[t][3] - mn1);
                    ls0 += sacc[t][0] + sacc[t][1];
                    ls1 += sacc[t][2] + sacc[t][3];
                }
                ls0 += __shfl_xor_sync(0xffffffffu, ls0, 1);
                ls0 += __shfl_xor_sync(0xffffffffu, ls0, 2);
                ls1 += __shfl_xor_sync(0xffffffffu, ls1, 1);
                ls1 += __shfl_xor_sync(0xffffffffu, ls1, 2);
                l0 = l0 * a0 + ls0;
                l1 = l1 * a1 + ls1;
#pragma unroll
                for (int j = 0; j < 8; j++) {
                    oacc[j][0] *= a0; oacc[j][1] *= a0;
                    oacc[j][2] *= a1; oacc[j][3] *= a1;
                }
            }

            // ---- O += P V (bf16x3, P from registers) ----
#pragma unroll
            for (int ks = 0; ks < 4; ks++) {
                uint32_t ah[4], al[4];
                ah[0] = packf(sacc[2*ks][0],   sacc[2*ks][1]);
                ah[1] = packf(sacc[2*ks][2],   sacc[2*ks][3]);
                ah[2] = packf(sacc[2*ks+1][0], sacc[2*ks+1][1]);
                ah[3] = packf(sacc[2*ks+1][2], sacc[2*ks+1][3]);
#pragma unroll
                for (int r = 0; r < 4; r++) {
                    float flo = __uint_as_float(ah[r] << 16);
                    float fhi = __uint_as_float(ah[r] & 0xffff0000u);
                    float s0 = sacc[2*ks + (r >> 1)][(r & 1) * 2 + 0];
                    float s1 = sacc[2*ks + (r >> 1)][(r & 1) * 2 + 1];
                    al[r] = packf(s0 - flo, s1 - fhi);
                }
                const uint32_t vrow = (ks * 16 + rowV_) * 128;
#pragma unroll
                for (int jb = 0; jb < 4; jb++) {
                    uint32_t voff = vrow + ((jb * 32 + gV) ^ vswz);
                    uint32_t vh4[4], vl4[4];
                    ldsm4t(vh4, sVh + voff);
                    ldsm4t(vl4, sVl + voff);
                    mma16816(oacc[2 * jb + 0], ah, &vh4[0]);
                    mma16816(oacc[2 * jb + 1], ah, &vh4[2]);
                    mma16816(oacc[2 * jb + 0], ah, &vl4[0]);
                    mma16816(oacc[2 * jb + 1], ah, &vl4[2]);
                    mma16816(oacc[2 * jb + 0], al, &vh4[0]);
                    mma16816(oacc[2 * jb + 1], al, &vh4[2]);
                }
            }
        }
        __syncthreads();   // stage reusable for prefetch next iteration
    }
#undef F_ISSUE

    // ---- epilogue ----
    {
        const int b = bh >> 4, h = bh & (NH - 1);
        const float i0 = 1.f / l0, i1 = 1.f / l1;
        const int t0 = q0 + wm + (lane >> 2);
        const int c0 = h * ND + (lane & 3) * 2;
#pragma unroll
        for (int j = 0; j < 8; j++) {
            float v0 = oacc[j][0] * i0, v1 = oacc[j][1] * i0;
            float v2 = oacc[j][2] * i1, v3 = oacc[j][3] * i1;
            uint32_t ph0 = packf(v0, v1), ph1 = packf(v2, v3);
            uint32_t pl0 = packf(v0 - __uint_as_float(ph0 << 16),
                                 v1 - __uint_as_float(ph0 & 0xffff0000u));
            uint32_t pl1 = packf(v2 - __uint_as_float(ph1 << 16),
                                 v3 - __uint_as_float(ph1 & 0xffff0000u));
            size_t o0 = (size_t)(b * NT + t0) * NC + c0 + j * 8;
            size_t o1 = (size_t)(b * NT + t0 + 8) * NC + c0 + j * 8;
            *(uint32_t*)(Yh_ + o0) = ph0;
            *(uint32_t*)(Yl_ + o0) = pl0;
            *(uint32_t*)(Yh_ + o1) = ph1;
            *(uint32_t*)(Yl_ + o1) = pl1;
        }
    }
}

// ---------------------------------------------------------------------------
extern "C" void kernel_launch(void* const* d_in, const int* in_sizes, int n_in,
                              void* d_out, int out_size)
{
    const float* x  = (const float*)d_in[0];
    const float* Wa = (const float*)d_in[1];
    const float* Wp = (const float*)d_in[2];
    float* out = (float*)d_out;

    float* qkv;
    __nv_bfloat16 *xh, *xl, *yh, *yl, *wah, *wal, *wph, *wpl;
    __nv_bfloat16 *qh, *ql, *kh, *kl, *vh, *vl;
    cudaGetSymbolAddress((void**)&qkv, g_qkv);
    cudaGetSymbolAddress((void**)&xh,  g_xh);
    cudaGetSymbolAddress((void**)&xl,  g_xl);
    cudaGetSymbolAddress((void**)&yh,  g_yh);
    cudaGetSymbolAddress((void**)&yl,  g_yl);
    cudaGetSymbolAddress((void**)&wah, g_wah);
    cudaGetSymbolAddress((void**)&wal, g_wal);
    cudaGetSymbolAddress((void**)&wph, g_wph);
    cudaGetSymbolAddress((void**)&wpl, g_wpl);
    cudaGetSymbolAddress((void**)&qh,  g_qh);
    cudaGetSymbolAddress((void**)&ql,  g_ql);
    cudaGetSymbolAddress((void**)&kh,  g_kh);
    cudaGetSymbolAddress((void**)&kl,  g_kl);
    cudaGetSymbolAddress((void**)&vh,  g_vh);
    cudaGetSymbolAddress((void**)&vl,  g_vl);

    const int gemm_smem = 98304;          // 3 stages x 32KB
    cudaFuncSetAttribute(gemm_mma, cudaFuncAttributeMaxDynamicSharedMemorySize, gemm_smem);
    const int flash_smem = 98304;         // Q 32KB + 2 stages x 32KB
    cudaFuncSetAttribute(flash_mma, cudaFuncAttributeMaxDynamicSharedMemorySize, flash_smem);

    // 0) input splits / weight transposes
    cvt_split<<<(NM * NC) / 1024, 256>>>(x, xh, xl);
    wt_split<<<dim3(3 * NC / 32, NC / 32), dim3(32, 8)>>>(Wa, wah, wal, NC, 3 * NC);
    wt_split<<<dim3(NC / 32, NC / 32), dim3(32, 8)>>>(Wp, wph, wpl, NC, NC);

    // 1) QKV = x @ W_attn
    gemm_mma<<<dim3(3 * NC / 128, NM / 128), 128, gemm_smem>>>(
        xh, xl, wah, wal, qkv, NM, 3 * NC, NC);

    // 2) RoPE + split to bf16 hi/lo heads
    rope_split<<<(NBH * NT * ND) / 256, 256>>>(qkv);

    // 3) Flash attention (causal) on tensor cores -> yh/yl
    flash_mma<<<dim3(NT / 128, NBH), 256, flash_smem>>>(
        qh, ql, kh, kl, vh, vl, yh, yl);

    // 4) out = y @ W_proj
    gemm_mma<<<dim3(NC / 128, NM / 128), 128, gemm_smem>>>(
        yh, yl, wph, wpl, out, NM, NC, NC);
}